// round 11
// baseline (speedup 1.0000x reference)
#include <cuda_runtime.h>
#include <cuda_fp16.h>
#include <math.h>
#include <stdint.h>
typedef __half hf;

#define NHEAD 12
#define ROWS  4096
#define HSs   1048576LL

// ---------------- scratch ----------------
__device__ __align__(16) hf    g_S  [50331648];
__device__ __align__(16) hf    g_P  [50331648];
__device__ __align__(16) hf    g_q  [3145728];
__device__ __align__(16) hf    g_k  [3145728];
__device__ __align__(16) hf    g_v  [3145728];
__device__ __align__(16) hf    g_h1 [3145728];
__device__ __align__(16) hf    g_a  [3145728];
__device__ __align__(16) hf    g_m  [3145728];
__device__ __align__(16) hf    g_f  [12582912];
__device__ __align__(16) float g_x2 [3145728], g_h2[3145728];
__device__ __align__(16) hf    g_w1 [1769472];
__device__ __align__(16) hf    g_w2 [589824];
__device__ __align__(16) hf    g_w3 [2359296];
__device__ __align__(16) hf    g_w4 [2359296];

__device__ __forceinline__ uint32_t smem_u32(const void* p){
    uint32_t a; asm("{ .reg .u64 t; cvta.to.shared.u64 t, %1; cvt.u32.u64 %0, t; }":"=r"(a):"l"(p)); return a;
}
#define LDM4(r0,r1,r2,r3,ad) asm volatile("ldmatrix.sync.aligned.m8n8.x4.shared.b16 {%0,%1,%2,%3},[%4];" \
    : "=r"(r0),"=r"(r1),"=r"(r2),"=r"(r3):"r"(ad))
#define LDM4T(r0,r1,r2,r3,ad) asm volatile("ldmatrix.sync.aligned.m8n8.x4.trans.shared.b16 {%0,%1,%2,%3},[%4];" \
    : "=r"(r0),"=r"(r1),"=r"(r2),"=r"(r3):"r"(ad))
#define MMA(d,a,b) asm volatile( \
    "mma.sync.aligned.m16n8k16.row.col.f32.f16.f16.f32 {%0,%1,%2,%3},{%4,%5,%6,%7},{%8,%9},{%0,%1,%2,%3};" \
    : "+f"((d)[0]),"+f"((d)[1]),"+f"((d)[2]),"+f"((d)[3]) \
    : "r"((a)[0]),"r"((a)[1]),"r"((a)[2]),"r"((a)[3]),"r"((b)[0]),"r"((b)[1]))
#define CPA(dst,src) asm volatile("cp.async.cg.shared.global [%0],[%1],16;"::"r"(dst),"l"(src))
#define CPCOMMIT()   asm volatile("cp.async.commit_group;":::"memory")
#define CPWAIT0()    asm volatile("cp.async.wait_group 0;":::"memory")
#define CPWAIT1()    asm volatile("cp.async.wait_group 1;":::"memory")

__device__ __forceinline__ void st_h2(hf* p, float a, float b){
    __half2 t; t.x=__float2half_rn(a); t.y=__float2half_rn(b); *(__half2*)p = t;
}

struct GP {
    const hf *Ah,*Bh;
    int K, lda, ldb;
    long long sAz, sBz, sOz;
    float alpha;
    const float *bias, *res;
    float *outf; int ldo;
    hf *o1; int ldoh;
    hf *kd,*vd;
};

// C[M,N] = A[M,K] @ op(B), single fp16 product.
// BT=true: B is [N,K] k-contig. BT=false: B is [K,N] n-contig (trans ldmatrix).
// 3-stage cp.async pipeline (degenerates gracefully for T==1).
// EPI: 0=alpha->fp16 batched, 1=QKV scatter, 2=AV->[B,N,C] fp16, 3=bias+res f32, 4=bias+gelu fp16
template<int BM,int BN,int BK,int EPI,bool BT>
__global__ void __launch_bounds__(256) mma_gemm(GP p){
    constexpr int WARPS_N = BN/32;
    constexpr int WARPS_M = 8/WARPS_N;
    constexpr int WM = BM/WARPS_M;
    constexpr int MT = WM/16;
    constexpr int APAD = BK+8;
    constexpr int BPAD = BT ? (BK+8) : (BN+8);
    constexpr int ABYT = BM*APAD*2;
    constexpr int BBYT = BT ? (BN*BPAD*2) : (BK*BPAD*2);
    constexpr int STG  = ABYT + BBYT;

    extern __shared__ char dsm[];
    const uint32_t sb = smem_u32(dsm);
    const int tid=threadIdx.x, wid=tid>>5, lane=tid&31;
    const int z=blockIdx.z, m0=blockIdx.y*BM, n0=blockIdx.x*BN;
    const int wm_=wid/WARPS_N, wn_=wid%WARPS_N;

    const hf* Ah=p.Ah+(long long)z*p.sAz;
    const hf* Bh=p.Bh+(long long)z*p.sBz;

    float acc[MT][4][4];
    #pragma unroll
    for(int i=0;i<MT;i++)
        #pragma unroll
        for(int j=0;j<4;j++)
            #pragma unroll
            for(int e=0;e<4;e++) acc[i][j][e]=0.f;

    auto load_stage=[&](int t,int s){
        const long long k0=(long long)t*BK;
        const uint32_t b0 = sb + s*STG;
        #pragma unroll
        for(int i=tid;i<BM*(BK/8);i+=256){
            int row=i/(BK/8), seg=i%(BK/8);
            uint32_t d = b0 + (row*APAD+seg*8)*2;
            long long g=(long long)(m0+row)*p.lda + k0 + seg*8;
            CPA(d, Ah+g);
        }
        if(BT){
            #pragma unroll
            for(int i=tid;i<BN*(BK/8);i+=256){
                int row=i/(BK/8), seg=i%(BK/8);
                uint32_t d=b0+ABYT+(row*BPAD+seg*8)*2;
                long long g=(long long)(n0+row)*p.ldb + k0 + seg*8;
                CPA(d, Bh+g);
            }
        } else {
            #pragma unroll
            for(int i=tid;i<BK*(BN/8);i+=256){
                int row=i/(BN/8), seg=i%(BN/8);
                uint32_t d=b0+ABYT+(row*BPAD+seg*8)*2;
                long long g=(long long)(k0+row)*p.ldb + n0 + seg*8;
                CPA(d, Bh+g);
            }
        }
        CPCOMMIT();
    };

    auto compute=[&](int s){
        const uint32_t bA=sb+s*STG, bB=bA+ABYT;
        #pragma unroll
        for(int kk=0;kk<BK;kk+=16){
            uint32_t bh[4][2];
            #pragma unroll
            for(int nt=0;nt<2;nt++){
                if(BT){
                    int row = wn_*32 + nt*16 + (lane&7) + ((lane>>4)&1)*8;
                    int ko  = kk + ((lane>>3)&1)*8;
                    uint32_t off=(uint32_t)(row*BPAD+ko)*2;
                    LDM4(bh[2*nt][0],bh[2*nt][1],bh[2*nt+1][0],bh[2*nt+1][1], bB+off);
                } else {
                    int kb = kk + (lane&7) + ((lane>>3)&1)*8;
                    int nb = wn_*32 + nt*16 + ((lane>>4)&1)*8;
                    uint32_t off=(uint32_t)(kb*BPAD+nb)*2;
                    LDM4T(bh[2*nt][0],bh[2*nt][1],bh[2*nt+1][0],bh[2*nt+1][1], bB+off);
                }
            }
            #pragma unroll
            for(int mi=0;mi<MT;mi++){
                int row = wm_*WM + mi*16 + (lane&7) + ((lane>>3)&1)*8;
                int ko  = kk + ((lane>>4)&1)*8;
                uint32_t off=(uint32_t)(row*APAD+ko)*2;
                uint32_t ah[4];
                LDM4(ah[0],ah[1],ah[2],ah[3], bA+off);
                #pragma unroll
                for(int ni=0;ni<4;ni++) MMA(acc[mi][ni],ah,bh[ni]);
            }
        }
    };

    const int T = p.K/BK;
    load_stage(0,0);
    if(T>1) load_stage(1,1);
    for(int t=0;t<T;t++){
        if(t+1<T){ CPWAIT1(); } else { CPWAIT0(); }
        __syncthreads();
        if(t+2<T) load_stage(t+2,(t+2)%3);
        compute(t%3);
    }

    // -------- epilogue --------
    const int rb = m0 + wm_*WM, cbse = n0 + wn_*32;
    #pragma unroll
    for(int mi=0;mi<MT;mi++){
        #pragma unroll
        for(int ni=0;ni<4;ni++){
            #pragma unroll
            for(int half=0;half<2;half++){
                int r = rb + mi*16 + (lane>>2) + half*8;
                int c = cbse + ni*8 + (lane&3)*2;
                float v0=acc[mi][ni][half*2], v1=acc[mi][ni][half*2+1];
                if(EPI==0){
                    st_h2(p.o1 + (long long)z*p.sOz + (long long)r*p.ldo + c,
                          v0*p.alpha, v1*p.alpha);
                } else if(EPI==1){
                    v0+=p.bias[c]; v1+=p.bias[c+1];
                    int b=r>>10, n=r&1023;
                    hf* dst = (c<768)?p.o1 : ((c<1536)?p.kd:p.vd);
                    int cc  = (c<768)?c   : ((c<1536)?c-768:c-1536);
                    int hh=cc>>6, d=cc&63;
                    long long o=((long long)(b*12+hh)*1024+n)*64+d;
                    st_h2(dst+o, v0, v1);
                } else if(EPI==2){
                    int b=z/12, hh=z-b*12;
                    long long o=(long long)(b*1024+r)*768 + hh*64 + c;
                    st_h2(p.o1+o, v0, v1);
                } else if(EPI==3){
                    long long o=(long long)r*p.ldo + c;
                    float2 rr=*(const float2*)(p.res+o);
                    float2 ov; ov.x=v0+p.bias[c]+rr.x; ov.y=v1+p.bias[c+1]+rr.y;
                    *(float2*)(p.outf+o)=ov;
                } else if(EPI==4){
                    v0+=p.bias[c]; v1+=p.bias[c+1];
                    v0=0.5f*v0*(1.0f+erff(v0*0.70710678118654752f));
                    v1=0.5f*v1*(1.0f+erff(v1*0.70710678118654752f));
                    st_h2(p.o1+(long long)r*p.ldoh+c, v0, v1);
                }
            }
        }
    }
}

// ---------------- LayerNorm body (callable) ----------------
__device__ __forceinline__ void ln_body(const float* x, const float* g, const float* b,
                                        float* outf, hf* oh, long long row, int tid){
    float xv[3], s=0.f, ss=0.f;
    #pragma unroll
    for(int i=0;i<3;i++){ float v=x[tid+i*256]; xv[i]=v; s+=v; ss+=v*v; }
    __shared__ float red[64];
    #pragma unroll
    for(int o=16;o>0;o>>=1){ s+=__shfl_down_sync(~0u,s,o); ss+=__shfl_down_sync(~0u,ss,o); }
    int warp=tid>>5, lane=tid&31;
    if(lane==0){ red[warp]=s; red[32+warp]=ss; }
    __syncthreads();
    if(warp==0){
        s=(lane<8)?red[lane]:0.f; ss=(lane<8)?red[32+lane]:0.f;
        #pragma unroll
        for(int o=4;o>0;o>>=1){ s+=__shfl_down_sync(~0u,s,o); ss+=__shfl_down_sync(~0u,ss,o); }
        if(lane==0){ red[0]=s; red[1]=ss; }
    }
    __syncthreads();
    float mu=red[0]*(1.f/768), var=red[1]*(1.f/768)-mu*mu, rstd=rsqrtf(var+1e-5f);
    #pragma unroll
    for(int i=0;i<3;i++){
        int c=tid+i*256;
        float v=(xv[i]-mu)*rstd*g[c]+b[c];
        long long o=row*768+c;
        if(outf) outf[o]=v;
        if(oh) oh[o]=__float2half_rn(v);
    }
}

__global__ void ln_kernel(const float* __restrict__ in, const float* __restrict__ g,
                          const float* __restrict__ b, float* __restrict__ outf,
                          hf* __restrict__ oh){
    ln_body(in + (long long)blockIdx.x*768, g, b, outf, oh, blockIdx.x, threadIdx.x);
}

// ---------------- fused wconv + ln1 ----------------
__global__ void pre_kernel(const float* __restrict__ x, const float* __restrict__ g1,
                           const float* __restrict__ be1, hf* __restrict__ oh,
                           const float* __restrict__ w1,const float* __restrict__ w2,
                           const float* __restrict__ w3,const float* __restrict__ w4,
                           hf* o1,hf* o2,hf* o3,hf* o4){
    int bid=blockIdx.x;
    if(bid<4096){
        ln_body(x + (long long)bid*768, g1, be1, nullptr, oh, bid, threadIdx.x);
    } else {
        int i=(bid-4096)*256+threadIdx.x;
        const float* s; hf *ohw; int j=i;
        if(j<1769472){ s=w1; ohw=o1; }
        else if((j-=1769472)<589824){ s=w2; ohw=o2; }
        else if((j-=589824)<2359296){ s=w3; ohw=o3; }
        else { j-=2359296; s=w4; ohw=o4; }
        ohw[j]=__float2half_rn(s[j]);
    }
}

// ---------------- fused mix->softmax->mix: scalar fp32 math, fp16 slab, reg-diet ----------------
__global__ void __launch_bounds__(256,3) mixsoftmax(
    const hf* __restrict__ S, hf* __restrict__ P,
    const float* __restrict__ tb, const float* __restrict__ ta){
    extern __shared__ hf sh[];                        // 12*1024 fp16 e-values
    __shared__ float tbs[144], tas[144], wsum[8][12], rin[12];
    int tid=threadIdx.x, warp=tid>>5, lane=tid&31;
    if(tid<144){ tbs[tid]=tb[tid]; tas[tid]=ta[tid]; }
    __syncthreads();
    int bn=blockIdx.x, b=bn>>10, n=bn&1023;
    long long base=((long long)b*NHEAD*1024+n)*1024;
    float sm[12];
    #pragma unroll
    for(int g=0;g<12;g++) sm[g]=0.f;
    #pragma unroll 1
    for(int j=0;j<4;j++){
        int m=tid+j*256;
        float s[12];
        #pragma unroll
        for(int h=0;h<12;h++) s[h]=__half2float(S[base+h*HSs+m]);
        #pragma unroll
        for(int g=0;g<12;g++){
            float v=0.f;
            #pragma unroll
            for(int h=0;h<12;h++) v=fmaf(tbs[g*12+h],s[h],v);
            float e=__expf(v);
            sh[g*1024+m]=__float2half_rn(e);
            sm[g]+=e;
        }
    }
    #pragma unroll
    for(int o=16;o>0;o>>=1){
        #pragma unroll
        for(int g=0;g<12;g++) sm[g]+=__shfl_xor_sync(~0u,sm[g],o);
    }
    if(lane==0){
        #pragma unroll
        for(int g=0;g<12;g++) wsum[warp][g]=sm[g];
    }
    __syncthreads();
    if(tid<12){
        float t=0.f;
        #pragma unroll
        for(int w=0;w<8;w++) t+=wsum[w][tid];
        rin[tid]=1.f/t;
    }
    __syncthreads();
    #pragma unroll 1
    for(int j=0;j<4;j++){
        int m=tid+j*256;
        float e[12];
        #pragma unroll
        for(int h=0;h<12;h++) e[h]=__half2float(sh[h*1024+m])*rin[h];
        #pragma unroll
        for(int g=0;g<12;g++){
            float v=0.f;
            #pragma unroll
            for(int h=0;h<12;h++) v=fmaf(tas[g*12+h],e[h],v);
            P[base+g*HSs+m]=__float2half_rn(v);
        }
    }
}

// ---------------- fused depthwise conv + LN(gm,bm) ----------------
__global__ void dwln_kernel(const float* __restrict__ in, const float* __restrict__ w,
                            const float* __restrict__ bias, const float* __restrict__ gm,
                            const float* __restrict__ bm, hf* __restrict__ om){
    int row=blockIdx.x, tid=threadIdx.x;
    int b=row>>10, n=row&1023;
    const float* xp = in + (long long)b*1024*768;
    float acc[3], s=0.f, ss=0.f;
    #pragma unroll
    for(int i=0;i<3;i++){
        int c=tid+i*256;
        float a=bias[c];
        #pragma unroll
        for(int k=0;k<7;k++){
            int m=n+k-3;
            if(m>=0 && m<1024) a+=w[c*7+k]*xp[(long long)m*768+c];
        }
        acc[i]=a; s+=a; ss+=a*a;
    }
    __shared__ float red[64];
    #pragma unroll
    for(int o=16;o>0;o>>=1){ s+=__shfl_down_sync(~0u,s,o); ss+=__shfl_down_sync(~0u,ss,o); }
    int warp=tid>>5, lane=tid&31;
    if(lane==0){ red[warp]=s; red[32+warp]=ss; }
    __syncthreads();
    if(warp==0){
        s=(lane<8)?red[lane]:0.f; ss=(lane<8)?red[32+lane]:0.f;
        #pragma unroll
        for(int o=4;o>0;o>>=1){ s+=__shfl_down_sync(~0u,s,o); ss+=__shfl_down_sync(~0u,ss,o); }
        if(lane==0){ red[0]=s; red[1]=ss; }
    }
    __syncthreads();
    float mu=red[0]*(1.f/768), var=red[1]*(1.f/768)-mu*mu, rstd=rsqrtf(var+1e-5f);
    #pragma unroll
    for(int i=0;i<3;i++){
        int c=tid+i*256;
        om[(long long)row*768+c]=__float2half_rn((acc[i]-mu)*rstd*gm[c]+bm[c]);
    }
}

// ---------------- launch ----------------
extern "C" void kernel_launch(void* const* d_in, const int* in_sizes, int n_in,
                              void* d_out, int out_size){
    const float *x=(const float*)d_in[0], *w_qkv=(const float*)d_in[1], *b_qkv=(const float*)d_in[2];
    const float *w_proj=(const float*)d_in[3], *b_proj=(const float*)d_in[4];
    const float *w_fc1=(const float*)d_in[5], *b_fc1=(const float*)d_in[6];
    const float *w_fc2=(const float*)d_in[7], *b_fc2=(const float*)d_in[8];
    const float *t_before=(const float*)d_in[9], *t_after=(const float*)d_in[10];
    const float *g1=(const float*)d_in[11], *be1=(const float*)d_in[12];
    const float *g2=(const float*)d_in[13], *be2=(const float*)d_in[14];
    const float *dw_w=(const float*)d_in[15], *dw_b=(const float*)d_in[16];
    const float *gm=(const float*)d_in[17], *bm=(const float*)d_in[18];
    float* out=(float*)d_out;

    float *px2,*ph2;
    hf *pS,*pP,*pq,*pk,*pv,*ph1,*pa,*pm,*pf,*w1,*w2,*w3,*w4;
    cudaGetSymbolAddress((void**)&pS,g_S);   cudaGetSymbolAddress((void**)&px2,g_x2);
    cudaGetSymbolAddress((void**)&ph2,g_h2);
    cudaGetSymbolAddress((void**)&pP,g_P);   cudaGetSymbolAddress((void**)&pq,g_q);
    cudaGetSymbolAddress((void**)&pk,g_k);   cudaGetSymbolAddress((void**)&pv,g_v);
    cudaGetSymbolAddress((void**)&ph1,g_h1); cudaGetSymbolAddress((void**)&pa,g_a);
    cudaGetSymbolAddress((void**)&pm,g_m);   cudaGetSymbolAddress((void**)&pf,g_f);
    cudaGetSymbolAddress((void**)&w1,g_w1);  cudaGetSymbolAddress((void**)&w2,g_w2);
    cudaGetSymbolAddress((void**)&w3,g_w3);  cudaGetSymbolAddress((void**)&w4,g_w4);

    // smem sizes
    const int S_QKV = 3*((128*40 + 128*40)*2);          // 61440
    const int S_QK  = 1*((128*72 + 64*72)*2);           // 27648
    const int S_AV  = 3*((64*40)*2 + (32*72)*2);        // 29184
    const int S_PRJ = 3*((64*40 + 128*40)*2);           // 46080
    const int S_FC1 = 3*((128*40 + 128*40)*2);          // 61440
    const int SMIX  = 12*1024*2;                         // 24576 (fp16 slab)
    cudaFuncSetAttribute(mma_gemm<128,128,32,1,true>, cudaFuncAttributeMaxDynamicSharedMemorySize, S_QKV);
    cudaFuncSetAttribute(mma_gemm<128,64,64,0,true>,  cudaFuncAttributeMaxDynamicSharedMemorySize, S_QK);
    cudaFuncSetAttribute(mma_gemm<64,64,32,2,false>,  cudaFuncAttributeMaxDynamicSharedMemorySize, S_AV);
    cudaFuncSetAttribute(mma_gemm<64,128,32,3,true>,  cudaFuncAttributeMaxDynamicSharedMemorySize, S_PRJ);
    cudaFuncSetAttribute(mma_gemm<128,128,32,4,true>, cudaFuncAttributeMaxDynamicSharedMemorySize, S_FC1);
    cudaFuncSetAttribute(mixsoftmax, cudaFuncAttributeMaxDynamicSharedMemorySize, SMIX);

    // fused ln1 + weight convert
    pre_kernel<<<4096+27648,256>>>(x,g1,be1,ph1, w_qkv,w_proj,w_fc1,w_fc2, w1,w2,w3,w4);

    GP p{};
    // QKV: h1 @ w_qkv^T + b -> q, k, v
    p.Ah=ph1; p.Bh=w1; p.K=768; p.lda=768; p.ldb=768;
    p.bias=b_qkv; p.o1=pq; p.kd=pk; p.vd=pv;
    mma_gemm<128,128,32,1,true><<<dim3(18,32,1),256,S_QKV>>>(p);

    // QK^T per (b,h): S = Q K^T * 0.125 — single-stage BK=64
    p=GP{}; p.Ah=pq; p.Bh=pk;
    p.K=64; p.lda=64; p.ldb=64; p.sAz=65536; p.sBz=65536; p.sOz=HSs;
    p.o1=pS; p.ldo=1024; p.alpha=0.125f;
    mma_gemm<128,64,64,0,true><<<dim3(16,8,48),256,S_QK>>>(p);

    mixsoftmax<<<ROWS,256,SMIX>>>(pS,pP,t_before,t_after);

    // AV per (b,h): P[1024,1024] @ V[1024,64] (B row-major via trans-ldmatrix)
    p=GP{}; p.Ah=pP; p.Bh=pv;
    p.K=1024; p.lda=1024; p.ldb=64; p.sAz=HSs; p.sBz=65536;
    p.o1=pa;
    mma_gemm<64,64,32,2,false><<<dim3(1,16,48),256,S_AV>>>(p);

    // proj + bias + residual(x) -> x2
    p=GP{}; p.Ah=pa; p.Bh=w2;
    p.K=768; p.lda=768; p.ldb=768; p.bias=b_proj; p.res=x; p.outf=px2; p.ldo=768;
    mma_gemm<64,128,32,3,true><<<dim3(6,64,1),256,S_PRJ>>>(p);

    ln_kernel<<<ROWS,256>>>(px2,g2,be2,ph2,nullptr);
    dwln_kernel<<<ROWS,256>>>(ph2,dw_w,dw_b,gm,bm,pm);

    // fc1 + bias + gelu -> f
    p=GP{}; p.Ah=pm; p.Bh=w3;
    p.K=768; p.lda=768; p.ldb=768; p.bias=b_fc1; p.o1=pf; p.ldoh=3072;
    mma_gemm<128,128,32,4,true><<<dim3(24,32,1),256,S_FC1>>>(p);

    // fc2 + bias + residual(x2) -> out
    p=GP{}; p.Ah=pf; p.Bh=w4;
    p.K=3072; p.lda=3072; p.ldb=3072; p.bias=b_fc2; p.res=px2; p.outf=out; p.ldo=768;
    mma_gemm<64,128,32,3,true><<<dim3(6,64,1),256,S_PRJ>>>(p);
}

// round 12
// speedup vs baseline: 1.2593x; 1.2593x over previous
#include <cuda_runtime.h>
#include <cuda_fp16.h>
#include <math.h>
#include <stdint.h>
typedef __half hf;

#define NHEAD 12
#define ROWS  4096
#define HSs   1048576LL

// ---------------- scratch ----------------
__device__ __align__(16) hf    g_S  [50331648];
__device__ __align__(16) hf    g_P  [50331648];
__device__ __align__(16) hf    g_q  [3145728];
__device__ __align__(16) hf    g_k  [3145728];
__device__ __align__(16) hf    g_v  [3145728];
__device__ __align__(16) hf    g_h1 [3145728];
__device__ __align__(16) hf    g_a  [3145728];
__device__ __align__(16) hf    g_m  [3145728];
__device__ __align__(16) hf    g_f  [12582912];
__device__ __align__(16) float g_x2 [3145728], g_h2[3145728];
__device__ __align__(16) hf    g_w1 [1769472];
__device__ __align__(16) hf    g_w2 [589824];
__device__ __align__(16) hf    g_w3 [2359296];
__device__ __align__(16) hf    g_w4 [2359296];

__device__ __forceinline__ uint32_t smem_u32(const void* p){
    uint32_t a; asm("{ .reg .u64 t; cvta.to.shared.u64 t, %1; cvt.u32.u64 %0, t; }":"=r"(a):"l"(p)); return a;
}
#define LDM4(r0,r1,r2,r3,ad) asm volatile("ldmatrix.sync.aligned.m8n8.x4.shared.b16 {%0,%1,%2,%3},[%4];" \
    : "=r"(r0),"=r"(r1),"=r"(r2),"=r"(r3):"r"(ad))
#define LDM4T(r0,r1,r2,r3,ad) asm volatile("ldmatrix.sync.aligned.m8n8.x4.trans.shared.b16 {%0,%1,%2,%3},[%4];" \
    : "=r"(r0),"=r"(r1),"=r"(r2),"=r"(r3):"r"(ad))
#define MMA(d,a,b) asm volatile( \
    "mma.sync.aligned.m16n8k16.row.col.f32.f16.f16.f32 {%0,%1,%2,%3},{%4,%5,%6,%7},{%8,%9},{%0,%1,%2,%3};" \
    : "+f"((d)[0]),"+f"((d)[1]),"+f"((d)[2]),"+f"((d)[3]) \
    : "r"((a)[0]),"r"((a)[1]),"r"((a)[2]),"r"((a)[3]),"r"((b)[0]),"r"((b)[1]))
#define CPA(dst,src) asm volatile("cp.async.cg.shared.global [%0],[%1],16;"::"r"(dst),"l"(src))
#define CPCOMMIT()   asm volatile("cp.async.commit_group;":::"memory")
#define CPWAIT0()    asm volatile("cp.async.wait_group 0;":::"memory")
#define CPWAIT1()    asm volatile("cp.async.wait_group 1;":::"memory")

__device__ __forceinline__ void st_h2(hf* p, float a, float b){
    __half2 t; t.x=__float2half_rn(a); t.y=__float2half_rn(b); *(__half2*)p = t;
}

struct GP {
    const hf *Ah,*Bh;
    int K, lda, ldb;
    long long sAz, sBz, sOz;
    float alpha;
    const float *bias, *res;
    float *outf; int ldo;
    hf *o1; int ldoh;
    hf *kd,*vd;
};

// C[M,N] = A[M,K] @ op(B), single fp16 product.
// BT=true: B is [N,K] k-contig. BT=false: B is [K,N] n-contig (trans ldmatrix).
// 3-stage cp.async pipeline (degenerates gracefully for T==1).
// EPI: 0=alpha->fp16 batched, 1=QKV scatter, 2=AV->[B,N,C] fp16, 3=bias+res f32, 4=bias+gelu fp16
template<int BM,int BN,int BK,int EPI,bool BT>
__global__ void __launch_bounds__(256) mma_gemm(GP p){
    constexpr int WARPS_N = BN/32;
    constexpr int WARPS_M = 8/WARPS_N;
    constexpr int WM = BM/WARPS_M;
    constexpr int MT = WM/16;
    constexpr int APAD = BK+8;
    constexpr int BPAD = BT ? (BK+8) : (BN+8);
    constexpr int ABYT = BM*APAD*2;
    constexpr int BBYT = BT ? (BN*BPAD*2) : (BK*BPAD*2);
    constexpr int STG  = ABYT + BBYT;

    extern __shared__ char dsm[];
    const uint32_t sb = smem_u32(dsm);
    const int tid=threadIdx.x, wid=tid>>5, lane=tid&31;
    const int z=blockIdx.z, m0=blockIdx.y*BM, n0=blockIdx.x*BN;
    const int wm_=wid/WARPS_N, wn_=wid%WARPS_N;

    const hf* Ah=p.Ah+(long long)z*p.sAz;
    const hf* Bh=p.Bh+(long long)z*p.sBz;

    float acc[MT][4][4];
    #pragma unroll
    for(int i=0;i<MT;i++)
        #pragma unroll
        for(int j=0;j<4;j++)
            #pragma unroll
            for(int e=0;e<4;e++) acc[i][j][e]=0.f;

    auto load_stage=[&](int t,int s){
        const long long k0=(long long)t*BK;
        const uint32_t b0 = sb + s*STG;
        #pragma unroll
        for(int i=tid;i<BM*(BK/8);i+=256){
            int row=i/(BK/8), seg=i%(BK/8);
            uint32_t d = b0 + (row*APAD+seg*8)*2;
            long long g=(long long)(m0+row)*p.lda + k0 + seg*8;
            CPA(d, Ah+g);
        }
        if(BT){
            #pragma unroll
            for(int i=tid;i<BN*(BK/8);i+=256){
                int row=i/(BK/8), seg=i%(BK/8);
                uint32_t d=b0+ABYT+(row*BPAD+seg*8)*2;
                long long g=(long long)(n0+row)*p.ldb + k0 + seg*8;
                CPA(d, Bh+g);
            }
        } else {
            #pragma unroll
            for(int i=tid;i<BK*(BN/8);i+=256){
                int row=i/(BN/8), seg=i%(BN/8);
                uint32_t d=b0+ABYT+(row*BPAD+seg*8)*2;
                long long g=(long long)(k0+row)*p.ldb + n0 + seg*8;
                CPA(d, Bh+g);
            }
        }
        CPCOMMIT();
    };

    auto compute=[&](int s){
        const uint32_t bA=sb+s*STG, bB=bA+ABYT;
        #pragma unroll
        for(int kk=0;kk<BK;kk+=16){
            uint32_t bh[4][2];
            #pragma unroll
            for(int nt=0;nt<2;nt++){
                if(BT){
                    int row = wn_*32 + nt*16 + (lane&7) + ((lane>>4)&1)*8;
                    int ko  = kk + ((lane>>3)&1)*8;
                    uint32_t off=(uint32_t)(row*BPAD+ko)*2;
                    LDM4(bh[2*nt][0],bh[2*nt][1],bh[2*nt+1][0],bh[2*nt+1][1], bB+off);
                } else {
                    int kb = kk + (lane&7) + ((lane>>3)&1)*8;
                    int nb = wn_*32 + nt*16 + ((lane>>4)&1)*8;
                    uint32_t off=(uint32_t)(kb*BPAD+nb)*2;
                    LDM4T(bh[2*nt][0],bh[2*nt][1],bh[2*nt+1][0],bh[2*nt+1][1], bB+off);
                }
            }
            #pragma unroll
            for(int mi=0;mi<MT;mi++){
                int row = wm_*WM + mi*16 + (lane&7) + ((lane>>3)&1)*8;
                int ko  = kk + ((lane>>4)&1)*8;
                uint32_t off=(uint32_t)(row*APAD+ko)*2;
                uint32_t ah[4];
                LDM4(ah[0],ah[1],ah[2],ah[3], bA+off);
                #pragma unroll
                for(int ni=0;ni<4;ni++) MMA(acc[mi][ni],ah,bh[ni]);
            }
        }
    };

    const int T = p.K/BK;
    load_stage(0,0);
    if(T>1) load_stage(1,1);
    for(int t=0;t<T;t++){
        if(t+1<T){ CPWAIT1(); } else { CPWAIT0(); }
        __syncthreads();
        if(t+2<T) load_stage(t+2,(t+2)%3);
        compute(t%3);
    }

    // -------- epilogue --------
    const int rb = m0 + wm_*WM, cbse = n0 + wn_*32;
    #pragma unroll
    for(int mi=0;mi<MT;mi++){
        #pragma unroll
        for(int ni=0;ni<4;ni++){
            #pragma unroll
            for(int half=0;half<2;half++){
                int r = rb + mi*16 + (lane>>2) + half*8;
                int c = cbse + ni*8 + (lane&3)*2;
                float v0=acc[mi][ni][half*2], v1=acc[mi][ni][half*2+1];
                if(EPI==0){
                    st_h2(p.o1 + (long long)z*p.sOz + (long long)r*p.ldo + c,
                          v0*p.alpha, v1*p.alpha);
                } else if(EPI==1){
                    v0+=p.bias[c]; v1+=p.bias[c+1];
                    int b=r>>10, n=r&1023;
                    hf* dst = (c<768)?p.o1 : ((c<1536)?p.kd:p.vd);
                    int cc  = (c<768)?c   : ((c<1536)?c-768:c-1536);
                    int hh=cc>>6, d=cc&63;
                    long long o=((long long)(b*12+hh)*1024+n)*64+d;
                    st_h2(dst+o, v0, v1);
                } else if(EPI==2){
                    int b=z/12, hh=z-b*12;
                    long long o=(long long)(b*1024+r)*768 + hh*64 + c;
                    st_h2(p.o1+o, v0, v1);
                } else if(EPI==3){
                    long long o=(long long)r*p.ldo + c;
                    float2 rr=*(const float2*)(p.res+o);
                    float2 ov; ov.x=v0+p.bias[c]+rr.x; ov.y=v1+p.bias[c+1]+rr.y;
                    *(float2*)(p.outf+o)=ov;
                } else if(EPI==4){
                    v0+=p.bias[c]; v1+=p.bias[c+1];
                    v0=0.5f*v0*(1.0f+erff(v0*0.70710678118654752f));
                    v1=0.5f*v1*(1.0f+erff(v1*0.70710678118654752f));
                    st_h2(p.o1+(long long)r*p.ldoh+c, v0, v1);
                }
            }
        }
    }
}

// ---------------- LayerNorm body (callable) ----------------
__device__ __forceinline__ void ln_body(const float* x, const float* g, const float* b,
                                        float* outf, hf* oh, long long row, int tid){
    float xv[3], s=0.f, ss=0.f;
    #pragma unroll
    for(int i=0;i<3;i++){ float v=x[tid+i*256]; xv[i]=v; s+=v; ss+=v*v; }
    __shared__ float red[64];
    #pragma unroll
    for(int o=16;o>0;o>>=1){ s+=__shfl_down_sync(~0u,s,o); ss+=__shfl_down_sync(~0u,ss,o); }
    int warp=tid>>5, lane=tid&31;
    if(lane==0){ red[warp]=s; red[32+warp]=ss; }
    __syncthreads();
    if(warp==0){
        s=(lane<8)?red[lane]:0.f; ss=(lane<8)?red[32+lane]:0.f;
        #pragma unroll
        for(int o=4;o>0;o>>=1){ s+=__shfl_down_sync(~0u,s,o); ss+=__shfl_down_sync(~0u,ss,o); }
        if(lane==0){ red[0]=s; red[1]=ss; }
    }
    __syncthreads();
    float mu=red[0]*(1.f/768), var=red[1]*(1.f/768)-mu*mu, rstd=rsqrtf(var+1e-5f);
    #pragma unroll
    for(int i=0;i<3;i++){
        int c=tid+i*256;
        float v=(xv[i]-mu)*rstd*g[c]+b[c];
        long long o=row*768+c;
        if(outf) outf[o]=v;
        if(oh) oh[o]=__float2half_rn(v);
    }
}

__global__ void ln_kernel(const float* __restrict__ in, const float* __restrict__ g,
                          const float* __restrict__ b, float* __restrict__ outf,
                          hf* __restrict__ oh){
    ln_body(in + (long long)blockIdx.x*768, g, b, outf, oh, blockIdx.x, threadIdx.x);
}

// ---------------- fused wconv + ln1 ----------------
__global__ void pre_kernel(const float* __restrict__ x, const float* __restrict__ g1,
                           const float* __restrict__ be1, hf* __restrict__ oh,
                           const float* __restrict__ w1,const float* __restrict__ w2,
                           const float* __restrict__ w3,const float* __restrict__ w4,
                           hf* o1,hf* o2,hf* o3,hf* o4){
    int bid=blockIdx.x;
    if(bid<4096){
        ln_body(x + (long long)bid*768, g1, be1, nullptr, oh, bid, threadIdx.x);
    } else {
        int i=(bid-4096)*256+threadIdx.x;
        const float* s; hf *ohw; int j=i;
        if(j<1769472){ s=w1; ohw=o1; }
        else if((j-=1769472)<589824){ s=w2; ohw=o2; }
        else if((j-=589824)<2359296){ s=w3; ohw=o3; }
        else { j-=2359296; s=w4; ohw=o4; }
        ohw[j]=__float2half_rn(s[j]);
    }
}

// ---------------- fused mix->softmax->mix: half2 I/O + fp16 slab, 2 blocks/SM ----------------
__global__ void __launch_bounds__(256,2) mixsoftmax(
    const hf* __restrict__ S, hf* __restrict__ P,
    const float* __restrict__ tb, const float* __restrict__ ta){
    extern __shared__ __half2 sh2[];                 // 12*512 half2
    __shared__ float tbs[144], tas[144], wsum[8][12], rin[12];
    int tid=threadIdx.x, warp=tid>>5, lane=tid&31;
    if(tid<144){ tbs[tid]=tb[tid]; tas[tid]=ta[tid]; }
    __syncthreads();
    int bn=blockIdx.x, b=bn>>10, n=bn&1023;
    long long base=((long long)b*NHEAD*1024+n)*1024;
    const __half2* Sb=(const __half2*)(S+base);
    __half2* Pb=(__half2*)(P+base);
    float sm[12];
    #pragma unroll
    for(int g=0;g<12;g++) sm[g]=0.f;
    #pragma unroll 1
    for(int jj=0;jj<2;jj++){
        int mp=tid+jj*256;                           // half2 index (2 m's)
        float2 s[12];
        #pragma unroll
        for(int h=0;h<12;h++) s[h]=__half22float2(Sb[(uint32_t)(h*524288)+mp]);
        #pragma unroll
        for(int g=0;g<12;g++){
            float v0=0.f, v1=0.f;
            #pragma unroll
            for(int h=0;h<12;h++){ v0=fmaf(tbs[g*12+h],s[h].x,v0); v1=fmaf(tbs[g*12+h],s[h].y,v1); }
            float e0=__expf(v0), e1=__expf(v1);
            sh2[g*512+mp]=__floats2half2_rn(e0,e1);
            sm[g]+=e0+e1;
        }
    }
    #pragma unroll
    for(int o=16;o>0;o>>=1){
        #pragma unroll
        for(int g=0;g<12;g++) sm[g]+=__shfl_xor_sync(~0u,sm[g],o);
    }
    if(lane==0){
        #pragma unroll
        for(int g=0;g<12;g++) wsum[warp][g]=sm[g];
    }
    __syncthreads();
    if(tid<12){
        float t=0.f;
        #pragma unroll
        for(int w=0;w<8;w++) t+=wsum[w][tid];
        rin[tid]=1.f/t;
    }
    __syncthreads();
    #pragma unroll 1
    for(int jj=0;jj<2;jj++){
        int mp=tid+jj*256;
        float2 e[12];
        #pragma unroll
        for(int h=0;h<12;h++){
            e[h]=__half22float2(sh2[h*512+mp]);
            float r=rin[h];
            e[h].x*=r; e[h].y*=r;
        }
        #pragma unroll
        for(int g=0;g<12;g++){
            float v0=0.f, v1=0.f;
            #pragma unroll
            for(int h=0;h<12;h++){ v0=fmaf(tas[g*12+h],e[h].x,v0); v1=fmaf(tas[g*12+h],e[h].y,v1); }
            Pb[(uint32_t)(g*524288)+mp]=__floats2half2_rn(v0,v1);
        }
    }
}

// ---------------- fused depthwise conv + LN(gm,bm) ----------------
__global__ void dwln_kernel(const float* __restrict__ in, const float* __restrict__ w,
                            const float* __restrict__ bias, const float* __restrict__ gm,
                            const float* __restrict__ bm, hf* __restrict__ om){
    int row=blockIdx.x, tid=threadIdx.x;
    int b=row>>10, n=row&1023;
    const float* xp = in + (long long)b*1024*768;
    float acc[3], s=0.f, ss=0.f;
    #pragma unroll
    for(int i=0;i<3;i++){
        int c=tid+i*256;
        float a=bias[c];
        #pragma unroll
        for(int k=0;k<7;k++){
            int m=n+k-3;
            if(m>=0 && m<1024) a+=w[c*7+k]*xp[(long long)m*768+c];
        }
        acc[i]=a; s+=a; ss+=a*a;
    }
    __shared__ float red[64];
    #pragma unroll
    for(int o=16;o>0;o>>=1){ s+=__shfl_down_sync(~0u,s,o); ss+=__shfl_down_sync(~0u,ss,o); }
    int warp=tid>>5, lane=tid&31;
    if(lane==0){ red[warp]=s; red[32+warp]=ss; }
    __syncthreads();
    if(warp==0){
        s=(lane<8)?red[lane]:0.f; ss=(lane<8)?red[32+lane]:0.f;
        #pragma unroll
        for(int o=4;o>0;o>>=1){ s+=__shfl_down_sync(~0u,s,o); ss+=__shfl_down_sync(~0u,ss,o); }
        if(lane==0){ red[0]=s; red[1]=ss; }
    }
    __syncthreads();
    float mu=red[0]*(1.f/768), var=red[1]*(1.f/768)-mu*mu, rstd=rsqrtf(var+1e-5f);
    #pragma unroll
    for(int i=0;i<3;i++){
        int c=tid+i*256;
        om[(long long)row*768+c]=__float2half_rn((acc[i]-mu)*rstd*gm[c]+bm[c]);
    }
}

// ---------------- launch ----------------
extern "C" void kernel_launch(void* const* d_in, const int* in_sizes, int n_in,
                              void* d_out, int out_size){
    const float *x=(const float*)d_in[0], *w_qkv=(const float*)d_in[1], *b_qkv=(const float*)d_in[2];
    const float *w_proj=(const float*)d_in[3], *b_proj=(const float*)d_in[4];
    const float *w_fc1=(const float*)d_in[5], *b_fc1=(const float*)d_in[6];
    const float *w_fc2=(const float*)d_in[7], *b_fc2=(const float*)d_in[8];
    const float *t_before=(const float*)d_in[9], *t_after=(const float*)d_in[10];
    const float *g1=(const float*)d_in[11], *be1=(const float*)d_in[12];
    const float *g2=(const float*)d_in[13], *be2=(const float*)d_in[14];
    const float *dw_w=(const float*)d_in[15], *dw_b=(const float*)d_in[16];
    const float *gm=(const float*)d_in[17], *bm=(const float*)d_in[18];
    float* out=(float*)d_out;

    float *px2,*ph2;
    hf *pS,*pP,*pq,*pk,*pv,*ph1,*pa,*pm,*pf,*w1,*w2,*w3,*w4;
    cudaGetSymbolAddress((void**)&pS,g_S);   cudaGetSymbolAddress((void**)&px2,g_x2);
    cudaGetSymbolAddress((void**)&ph2,g_h2);
    cudaGetSymbolAddress((void**)&pP,g_P);   cudaGetSymbolAddress((void**)&pq,g_q);
    cudaGetSymbolAddress((void**)&pk,g_k);   cudaGetSymbolAddress((void**)&pv,g_v);
    cudaGetSymbolAddress((void**)&ph1,g_h1); cudaGetSymbolAddress((void**)&pa,g_a);
    cudaGetSymbolAddress((void**)&pm,g_m);   cudaGetSymbolAddress((void**)&pf,g_f);
    cudaGetSymbolAddress((void**)&w1,g_w1);  cudaGetSymbolAddress((void**)&w2,g_w2);
    cudaGetSymbolAddress((void**)&w3,g_w3);  cudaGetSymbolAddress((void**)&w4,g_w4);

    // smem sizes
    const int S_QKV = 3*((128*40 + 128*40)*2);          // 61440
    const int S_QK  = 1*((128*72 + 64*72)*2);           // 27648
    const int S_AV  = 3*((64*40)*2 + (32*72)*2);        // 29184
    const int S_PRJ = 3*((64*40 + 128*40)*2);           // 46080
    const int S_FC1 = 3*((128*40 + 128*40)*2);          // 61440
    const int SMIX  = 12*512*4;                          // 24576 (half2 slab)
    cudaFuncSetAttribute(mma_gemm<128,128,32,1,true>, cudaFuncAttributeMaxDynamicSharedMemorySize, S_QKV);
    cudaFuncSetAttribute(mma_gemm<128,64,64,0,true>,  cudaFuncAttributeMaxDynamicSharedMemorySize, S_QK);
    cudaFuncSetAttribute(mma_gemm<64,64,32,2,false>,  cudaFuncAttributeMaxDynamicSharedMemorySize, S_AV);
    cudaFuncSetAttribute(mma_gemm<64,128,32,3,true>,  cudaFuncAttributeMaxDynamicSharedMemorySize, S_PRJ);
    cudaFuncSetAttribute(mma_gemm<128,128,32,4,true>, cudaFuncAttributeMaxDynamicSharedMemorySize, S_FC1);
    cudaFuncSetAttribute(mixsoftmax, cudaFuncAttributeMaxDynamicSharedMemorySize, SMIX);

    // fused ln1 + weight convert
    pre_kernel<<<4096+27648,256>>>(x,g1,be1,ph1, w_qkv,w_proj,w_fc1,w_fc2, w1,w2,w3,w4);

    GP p{};
    // QKV: h1 @ w_qkv^T + b -> q, k, v
    p.Ah=ph1; p.Bh=w1; p.K=768; p.lda=768; p.ldb=768;
    p.bias=b_qkv; p.o1=pq; p.kd=pk; p.vd=pv;
    mma_gemm<128,128,32,1,true><<<dim3(18,32,1),256,S_QKV>>>(p);

    // QK^T per (b,h): S = Q K^T * 0.125 — single-stage BK=64
    p=GP{}; p.Ah=pq; p.Bh=pk;
    p.K=64; p.lda=64; p.ldb=64; p.sAz=65536; p.sBz=65536; p.sOz=HSs;
    p.o1=pS; p.ldo=1024; p.alpha=0.125f;
    mma_gemm<128,64,64,0,true><<<dim3(16,8,48),256,S_QK>>>(p);

    mixsoftmax<<<ROWS,256,SMIX>>>(pS,pP,t_before,t_after);

    // AV per (b,h): P[1024,1024] @ V[1024,64] (B row-major via trans-ldmatrix)
    p=GP{}; p.Ah=pP; p.Bh=pv;
    p.K=1024; p.lda=1024; p.ldb=64; p.sAz=HSs; p.sBz=65536;
    p.o1=pa;
    mma_gemm<64,64,32,2,false><<<dim3(1,16,48),256,S_AV>>>(p);

    // proj + bias + residual(x) -> x2
    p=GP{}; p.Ah=pa; p.Bh=w2;
    p.K=768; p.lda=768; p.ldb=768; p.bias=b_proj; p.res=x; p.outf=px2; p.ldo=768;
    mma_gemm<64,128,32,3,true><<<dim3(6,64,1),256,S_PRJ>>>(p);

    ln_kernel<<<ROWS,256>>>(px2,g2,be2,ph2,nullptr);
    dwln_kernel<<<ROWS,256>>>(ph2,dw_w,dw_b,gm,bm,pm);

    // fc1 + bias + gelu -> f
    p=GP{}; p.Ah=pm; p.Bh=w3;
    p.K=768; p.lda=768; p.ldb=768; p.bias=b_fc1; p.o1=pf; p.ldoh=3072;
    mma_gemm<128,128,32,4,true><<<dim3(24,32,1),256,S_FC1>>>(p);

    // fc2 + bias + residual(x2) -> out
    p=GP{}; p.Ah=pf; p.Bh=w4;
    p.K=3072; p.lda=3072; p.ldb=3072; p.bias=b_fc2; p.res=px2; p.outf=out; p.ldo=768;
    mma_gemm<64,128,32,3,true><<<dim3(6,64,1),256,S_PRJ>>>(p);
}

// round 13
// speedup vs baseline: 1.6330x; 1.2968x over previous
#include <cuda_runtime.h>
#include <cuda_fp16.h>
#include <math.h>
#include <stdint.h>
typedef __half hf;

#define NHEAD 12
#define ROWS  4096
#define HSs   1048576LL

// ---------------- scratch ----------------
__device__ __align__(16) hf    g_S  [50331648];
__device__ __align__(16) hf    g_P  [50331648];
__device__ __align__(16) hf    g_q  [3145728];
__device__ __align__(16) hf    g_k  [3145728];
__device__ __align__(16) hf    g_v  [3145728];
__device__ __align__(16) hf    g_h1 [3145728];
__device__ __align__(16) hf    g_a  [3145728];
__device__ __align__(16) hf    g_m  [3145728];
__device__ __align__(16) hf    g_f  [12582912];
__device__ __align__(16) float g_x2 [3145728], g_h2[3145728];
__device__ __align__(16) hf    g_w1 [1769472];
__device__ __align__(16) hf    g_w2 [589824];
__device__ __align__(16) hf    g_w3 [2359296];
__device__ __align__(16) hf    g_w4 [2359296];

__device__ __forceinline__ uint32_t smem_u32(const void* p){
    uint32_t a; asm("{ .reg .u64 t; cvta.to.shared.u64 t, %1; cvt.u32.u64 %0, t; }":"=r"(a):"l"(p)); return a;
}
#define LDM4(r0,r1,r2,r3,ad) asm volatile("ldmatrix.sync.aligned.m8n8.x4.shared.b16 {%0,%1,%2,%3},[%4];" \
    : "=r"(r0),"=r"(r1),"=r"(r2),"=r"(r3):"r"(ad))
#define LDM4T(r0,r1,r2,r3,ad) asm volatile("ldmatrix.sync.aligned.m8n8.x4.trans.shared.b16 {%0,%1,%2,%3},[%4];" \
    : "=r"(r0),"=r"(r1),"=r"(r2),"=r"(r3):"r"(ad))
#define MMA(d,a,b) asm volatile( \
    "mma.sync.aligned.m16n8k16.row.col.f32.f16.f16.f32 {%0,%1,%2,%3},{%4,%5,%6,%7},{%8,%9},{%0,%1,%2,%3};" \
    : "+f"((d)[0]),"+f"((d)[1]),"+f"((d)[2]),"+f"((d)[3]) \
    : "r"((a)[0]),"r"((a)[1]),"r"((a)[2]),"r"((a)[3]),"r"((b)[0]),"r"((b)[1]))
#define CPA(dst,src) asm volatile("cp.async.cg.shared.global [%0],[%1],16;"::"r"(dst),"l"(src))
#define CPCOMMIT()   asm volatile("cp.async.commit_group;":::"memory")
#define CPWAIT0()    asm volatile("cp.async.wait_group 0;":::"memory")
#define CPWAIT1()    asm volatile("cp.async.wait_group 1;":::"memory")

__device__ __forceinline__ void st_h2(hf* p, float a, float b){
    __half2 t; t.x=__float2half_rn(a); t.y=__float2half_rn(b); *(__half2*)p = t;
}

struct GP {
    const hf *Ah,*Bh;
    int K, lda, ldb;
    long long sAz, sBz, sOz;
    float alpha;
    const float *bias, *res;
    float *outf; int ldo;
    hf *o1; int ldoh;
    hf *kd,*vd;
};

// C[M,N] = A[M,K] @ op(B), single fp16 product.
// BT=true: B is [N,K] k-contig. BT=false: B is [K,N] n-contig (trans ldmatrix).
// 3-stage cp.async pipeline (degenerates gracefully for T==1).
// EPI: 0=alpha->fp16 batched, 1=QKV scatter, 2=AV->[B,N,C] fp16, 3=bias+res f32, 4=bias+gelu fp16
template<int BM,int BN,int BK,int EPI,bool BT>
__global__ void __launch_bounds__(256) mma_gemm(GP p){
    constexpr int WARPS_N = BN/32;
    constexpr int WARPS_M = 8/WARPS_N;
    constexpr int WM = BM/WARPS_M;
    constexpr int MT = WM/16;
    constexpr int APAD = BK+8;
    constexpr int BPAD = BT ? (BK+8) : (BN+8);
    constexpr int ABYT = BM*APAD*2;
    constexpr int BBYT = BT ? (BN*BPAD*2) : (BK*BPAD*2);
    constexpr int STG  = ABYT + BBYT;

    extern __shared__ char dsm[];
    const uint32_t sb = smem_u32(dsm);
    const int tid=threadIdx.x, wid=tid>>5, lane=tid&31;
    const int z=blockIdx.z, m0=blockIdx.y*BM, n0=blockIdx.x*BN;
    const int wm_=wid/WARPS_N, wn_=wid%WARPS_N;

    const hf* Ah=p.Ah+(long long)z*p.sAz;
    const hf* Bh=p.Bh+(long long)z*p.sBz;

    float acc[MT][4][4];
    #pragma unroll
    for(int i=0;i<MT;i++)
        #pragma unroll
        for(int j=0;j<4;j++)
            #pragma unroll
            for(int e=0;e<4;e++) acc[i][j][e]=0.f;

    auto load_stage=[&](int t,int s){
        const long long k0=(long long)t*BK;
        const uint32_t b0 = sb + s*STG;
        #pragma unroll
        for(int i=tid;i<BM*(BK/8);i+=256){
            int row=i/(BK/8), seg=i%(BK/8);
            uint32_t d = b0 + (row*APAD+seg*8)*2;
            long long g=(long long)(m0+row)*p.lda + k0 + seg*8;
            CPA(d, Ah+g);
        }
        if(BT){
            #pragma unroll
            for(int i=tid;i<BN*(BK/8);i+=256){
                int row=i/(BK/8), seg=i%(BK/8);
                uint32_t d=b0+ABYT+(row*BPAD+seg*8)*2;
                long long g=(long long)(n0+row)*p.ldb + k0 + seg*8;
                CPA(d, Bh+g);
            }
        } else {
            #pragma unroll
            for(int i=tid;i<BK*(BN/8);i+=256){
                int row=i/(BN/8), seg=i%(BN/8);
                uint32_t d=b0+ABYT+(row*BPAD+seg*8)*2;
                long long g=(long long)(k0+row)*p.ldb + n0 + seg*8;
                CPA(d, Bh+g);
            }
        }
        CPCOMMIT();
    };

    auto compute=[&](int s){
        const uint32_t bA=sb+s*STG, bB=bA+ABYT;
        #pragma unroll
        for(int kk=0;kk<BK;kk+=16){
            uint32_t bh[4][2];
            #pragma unroll
            for(int nt=0;nt<2;nt++){
                if(BT){
                    int row = wn_*32 + nt*16 + (lane&7) + ((lane>>4)&1)*8;
                    int ko  = kk + ((lane>>3)&1)*8;
                    uint32_t off=(uint32_t)(row*BPAD+ko)*2;
                    LDM4(bh[2*nt][0],bh[2*nt][1],bh[2*nt+1][0],bh[2*nt+1][1], bB+off);
                } else {
                    int kb = kk + (lane&7) + ((lane>>3)&1)*8;
                    int nb = wn_*32 + nt*16 + ((lane>>4)&1)*8;
                    uint32_t off=(uint32_t)(kb*BPAD+nb)*2;
                    LDM4T(bh[2*nt][0],bh[2*nt][1],bh[2*nt+1][0],bh[2*nt+1][1], bB+off);
                }
            }
            #pragma unroll
            for(int mi=0;mi<MT;mi++){
                int row = wm_*WM + mi*16 + (lane&7) + ((lane>>3)&1)*8;
                int ko  = kk + ((lane>>4)&1)*8;
                uint32_t off=(uint32_t)(row*APAD+ko)*2;
                uint32_t ah[4];
                LDM4(ah[0],ah[1],ah[2],ah[3], bA+off);
                #pragma unroll
                for(int ni=0;ni<4;ni++) MMA(acc[mi][ni],ah,bh[ni]);
            }
        }
    };

    const int T = p.K/BK;
    load_stage(0,0);
    if(T>1) load_stage(1,1);
    for(int t=0;t<T;t++){
        if(t+1<T){ CPWAIT1(); } else { CPWAIT0(); }
        __syncthreads();
        if(t+2<T) load_stage(t+2,(t+2)%3);
        compute(t%3);
    }

    // -------- epilogue --------
    const int rb = m0 + wm_*WM, cbse = n0 + wn_*32;
    #pragma unroll
    for(int mi=0;mi<MT;mi++){
        #pragma unroll
        for(int ni=0;ni<4;ni++){
            #pragma unroll
            for(int half=0;half<2;half++){
                int r = rb + mi*16 + (lane>>2) + half*8;
                int c = cbse + ni*8 + (lane&3)*2;
                float v0=acc[mi][ni][half*2], v1=acc[mi][ni][half*2+1];
                if(EPI==0){
                    st_h2(p.o1 + (long long)z*p.sOz + (long long)r*p.ldo + c,
                          v0*p.alpha, v1*p.alpha);
                } else if(EPI==1){
                    v0+=p.bias[c]; v1+=p.bias[c+1];
                    int b=r>>10, n=r&1023;
                    hf* dst = (c<768)?p.o1 : ((c<1536)?p.kd:p.vd);
                    int cc  = (c<768)?c   : ((c<1536)?c-768:c-1536);
                    int hh=cc>>6, d=cc&63;
                    long long o=((long long)(b*12+hh)*1024+n)*64+d;
                    st_h2(dst+o, v0, v1);
                } else if(EPI==2){
                    int b=z/12, hh=z-b*12;
                    long long o=(long long)(b*1024+r)*768 + hh*64 + c;
                    st_h2(p.o1+o, v0, v1);
                } else if(EPI==3){
                    long long o=(long long)r*p.ldo + c;
                    float2 rr=*(const float2*)(p.res+o);
                    float2 ov; ov.x=v0+p.bias[c]+rr.x; ov.y=v1+p.bias[c+1]+rr.y;
                    *(float2*)(p.outf+o)=ov;
                } else if(EPI==4){
                    v0+=p.bias[c]; v1+=p.bias[c+1];
                    v0=0.5f*v0*(1.0f+erff(v0*0.70710678118654752f));
                    v1=0.5f*v1*(1.0f+erff(v1*0.70710678118654752f));
                    st_h2(p.o1+(long long)r*p.ldoh+c, v0, v1);
                }
            }
        }
    }
}

// ---------------- LayerNorm body (callable) ----------------
__device__ __forceinline__ void ln_body(const float* x, const float* g, const float* b,
                                        float* outf, hf* oh, long long row, int tid){
    float xv[3], s=0.f, ss=0.f;
    #pragma unroll
    for(int i=0;i<3;i++){ float v=x[tid+i*256]; xv[i]=v; s+=v; ss+=v*v; }
    __shared__ float red[64];
    #pragma unroll
    for(int o=16;o>0;o>>=1){ s+=__shfl_down_sync(~0u,s,o); ss+=__shfl_down_sync(~0u,ss,o); }
    int warp=tid>>5, lane=tid&31;
    if(lane==0){ red[warp]=s; red[32+warp]=ss; }
    __syncthreads();
    if(warp==0){
        s=(lane<8)?red[lane]:0.f; ss=(lane<8)?red[32+lane]:0.f;
        #pragma unroll
        for(int o=4;o>0;o>>=1){ s+=__shfl_down_sync(~0u,s,o); ss+=__shfl_down_sync(~0u,ss,o); }
        if(lane==0){ red[0]=s; red[1]=ss; }
    }
    __syncthreads();
    float mu=red[0]*(1.f/768), var=red[1]*(1.f/768)-mu*mu, rstd=rsqrtf(var+1e-5f);
    #pragma unroll
    for(int i=0;i<3;i++){
        int c=tid+i*256;
        float v=(xv[i]-mu)*rstd*g[c]+b[c];
        long long o=row*768+c;
        if(outf) outf[o]=v;
        if(oh) oh[o]=__float2half_rn(v);
    }
}

__global__ void ln_kernel(const float* __restrict__ in, const float* __restrict__ g,
                          const float* __restrict__ b, float* __restrict__ outf,
                          hf* __restrict__ oh){
    ln_body(in + (long long)blockIdx.x*768, g, b, outf, oh, blockIdx.x, threadIdx.x);
}

// ---------------- fused wconv + ln1 ----------------
__global__ void pre_kernel(const float* __restrict__ x, const float* __restrict__ g1,
                           const float* __restrict__ be1, hf* __restrict__ oh,
                           const float* __restrict__ w1,const float* __restrict__ w2,
                           const float* __restrict__ w3,const float* __restrict__ w4,
                           hf* o1,hf* o2,hf* o3,hf* o4){
    int bid=blockIdx.x;
    if(bid<4096){
        ln_body(x + (long long)bid*768, g1, be1, nullptr, oh, bid, threadIdx.x);
    } else {
        int i=(bid-4096)*256+threadIdx.x;
        const float* s; hf *ohw; int j=i;
        if(j<1769472){ s=w1; ohw=o1; }
        else if((j-=1769472)<589824){ s=w2; ohw=o2; }
        else if((j-=589824)<2359296){ s=w3; ohw=o3; }
        else { j-=2359296; s=w4; ohw=o4; }
        ohw[j]=__float2half_rn(s[j]);
    }
}

// ---------------- fused mix->softmax->mix: 512 threads, one half2 column/thread ----------------
__global__ void __launch_bounds__(512) mixsoftmax(
    const hf* __restrict__ S, hf* __restrict__ P,
    const float* __restrict__ tb, const float* __restrict__ ta){
    extern __shared__ __half2 sh2[];                 // 12*512 half2
    __shared__ float tbs[144], tas[144], wsum[16][12], rin[12];
    int tid=threadIdx.x, warp=tid>>5, lane=tid&31;
    if(tid<144){ tbs[tid]=tb[tid]; tas[tid]=ta[tid]; }
    __syncthreads();
    int bn=blockIdx.x, b=bn>>10, n=bn&1023;
    long long base=((long long)b*NHEAD*1024+n)*1024;
    const __half2* Sb=(const __half2*)(S+base);
    __half2* Pb=(__half2*)(P+base);
    const int mp=tid;                                // one half2 column per thread
    float sm[12];
    {
        float2 s[12];
        #pragma unroll
        for(int h=0;h<12;h++) s[h]=__half22float2(Sb[(uint32_t)(h*524288)+mp]);
        #pragma unroll
        for(int g=0;g<12;g++){
            float v0=0.f, v1=0.f;
            #pragma unroll
            for(int h=0;h<12;h++){ v0=fmaf(tbs[g*12+h],s[h].x,v0); v1=fmaf(tbs[g*12+h],s[h].y,v1); }
            float e0=__expf(v0), e1=__expf(v1);
            sh2[g*512+mp]=__floats2half2_rn(e0,e1);
            sm[g]=e0+e1;
        }
    }
    #pragma unroll
    for(int o=16;o>0;o>>=1){
        #pragma unroll
        for(int g=0;g<12;g++) sm[g]+=__shfl_xor_sync(~0u,sm[g],o);
    }
    if(lane==0){
        #pragma unroll
        for(int g=0;g<12;g++) wsum[warp][g]=sm[g];
    }
    __syncthreads();
    if(tid<12){
        float t=0.f;
        #pragma unroll
        for(int w=0;w<16;w++) t+=wsum[w][tid];
        rin[tid]=1.f/t;
    }
    __syncthreads();
    {
        float2 e[12];
        #pragma unroll
        for(int h=0;h<12;h++){
            e[h]=__half22float2(sh2[h*512+mp]);
            float r=rin[h];
            e[h].x*=r; e[h].y*=r;
        }
        #pragma unroll
        for(int g=0;g<12;g++){
            float v0=0.f, v1=0.f;
            #pragma unroll
            for(int h=0;h<12;h++){ v0=fmaf(tas[g*12+h],e[h].x,v0); v1=fmaf(tas[g*12+h],e[h].y,v1); }
            Pb[(uint32_t)(g*524288)+mp]=__floats2half2_rn(v0,v1);
        }
    }
}

// ---------------- fused depthwise conv + LN(gm,bm) ----------------
__global__ void dwln_kernel(const float* __restrict__ in, const float* __restrict__ w,
                            const float* __restrict__ bias, const float* __restrict__ gm,
                            const float* __restrict__ bm, hf* __restrict__ om){
    int row=blockIdx.x, tid=threadIdx.x;
    int b=row>>10, n=row&1023;
    const float* xp = in + (long long)b*1024*768;
    float acc[3], s=0.f, ss=0.f;
    #pragma unroll
    for(int i=0;i<3;i++){
        int c=tid+i*256;
        float a=bias[c];
        #pragma unroll
        for(int k=0;k<7;k++){
            int m=n+k-3;
            if(m>=0 && m<1024) a+=w[c*7+k]*xp[(long long)m*768+c];
        }
        acc[i]=a; s+=a; ss+=a*a;
    }
    __shared__ float red[64];
    #pragma unroll
    for(int o=16;o>0;o>>=1){ s+=__shfl_down_sync(~0u,s,o); ss+=__shfl_down_sync(~0u,ss,o); }
    int warp=tid>>5, lane=tid&31;
    if(lane==0){ red[warp]=s; red[32+warp]=ss; }
    __syncthreads();
    if(warp==0){
        s=(lane<8)?red[lane]:0.f; ss=(lane<8)?red[32+lane]:0.f;
        #pragma unroll
        for(int o=4;o>0;o>>=1){ s+=__shfl_down_sync(~0u,s,o); ss+=__shfl_down_sync(~0u,ss,o); }
        if(lane==0){ red[0]=s; red[1]=ss; }
    }
    __syncthreads();
    float mu=red[0]*(1.f/768), var=red[1]*(1.f/768)-mu*mu, rstd=rsqrtf(var+1e-5f);
    #pragma unroll
    for(int i=0;i<3;i++){
        int c=tid+i*256;
        om[(long long)row*768+c]=__float2half_rn((acc[i]-mu)*rstd*gm[c]+bm[c]);
    }
}

// ---------------- launch ----------------
extern "C" void kernel_launch(void* const* d_in, const int* in_sizes, int n_in,
                              void* d_out, int out_size){
    const float *x=(const float*)d_in[0], *w_qkv=(const float*)d_in[1], *b_qkv=(const float*)d_in[2];
    const float *w_proj=(const float*)d_in[3], *b_proj=(const float*)d_in[4];
    const float *w_fc1=(const float*)d_in[5], *b_fc1=(const float*)d_in[6];
    const float *w_fc2=(const float*)d_in[7], *b_fc2=(const float*)d_in[8];
    const float *t_before=(const float*)d_in[9], *t_after=(const float*)d_in[10];
    const float *g1=(const float*)d_in[11], *be1=(const float*)d_in[12];
    const float *g2=(const float*)d_in[13], *be2=(const float*)d_in[14];
    const float *dw_w=(const float*)d_in[15], *dw_b=(const float*)d_in[16];
    const float *gm=(const float*)d_in[17], *bm=(const float*)d_in[18];
    float* out=(float*)d_out;

    float *px2,*ph2;
    hf *pS,*pP,*pq,*pk,*pv,*ph1,*pa,*pm,*pf,*w1,*w2,*w3,*w4;
    cudaGetSymbolAddress((void**)&pS,g_S);   cudaGetSymbolAddress((void**)&px2,g_x2);
    cudaGetSymbolAddress((void**)&ph2,g_h2);
    cudaGetSymbolAddress((void**)&pP,g_P);   cudaGetSymbolAddress((void**)&pq,g_q);
    cudaGetSymbolAddress((void**)&pk,g_k);   cudaGetSymbolAddress((void**)&pv,g_v);
    cudaGetSymbolAddress((void**)&ph1,g_h1); cudaGetSymbolAddress((void**)&pa,g_a);
    cudaGetSymbolAddress((void**)&pm,g_m);   cudaGetSymbolAddress((void**)&pf,g_f);
    cudaGetSymbolAddress((void**)&w1,g_w1);  cudaGetSymbolAddress((void**)&w2,g_w2);
    cudaGetSymbolAddress((void**)&w3,g_w3);  cudaGetSymbolAddress((void**)&w4,g_w4);

    // smem sizes
    const int S_QKV = 3*((128*40 + 128*40)*2);          // 61440
    const int S_QK  = 1*((128*72 + 64*72)*2);           // 27648
    const int S_AV  = 3*((64*40)*2 + (32*72)*2);        // 29184
    const int S_PRJ = 3*((64*40 + 128*40)*2);           // 46080
    const int S_FC1 = 3*((128*40 + 128*40)*2);          // 61440
    const int SMIX  = 12*512*4;                          // 24576 (half2 slab)
    cudaFuncSetAttribute(mma_gemm<128,128,32,1,true>, cudaFuncAttributeMaxDynamicSharedMemorySize, S_QKV);
    cudaFuncSetAttribute(mma_gemm<128,64,64,0,true>,  cudaFuncAttributeMaxDynamicSharedMemorySize, S_QK);
    cudaFuncSetAttribute(mma_gemm<64,64,32,2,false>,  cudaFuncAttributeMaxDynamicSharedMemorySize, S_AV);
    cudaFuncSetAttribute(mma_gemm<64,128,32,3,true>,  cudaFuncAttributeMaxDynamicSharedMemorySize, S_PRJ);
    cudaFuncSetAttribute(mma_gemm<128,128,32,4,true>, cudaFuncAttributeMaxDynamicSharedMemorySize, S_FC1);
    cudaFuncSetAttribute(mixsoftmax, cudaFuncAttributeMaxDynamicSharedMemorySize, SMIX);

    // fused ln1 + weight convert
    pre_kernel<<<4096+27648,256>>>(x,g1,be1,ph1, w_qkv,w_proj,w_fc1,w_fc2, w1,w2,w3,w4);

    GP p{};
    // QKV: h1 @ w_qkv^T + b -> q, k, v
    p.Ah=ph1; p.Bh=w1; p.K=768; p.lda=768; p.ldb=768;
    p.bias=b_qkv; p.o1=pq; p.kd=pk; p.vd=pv;
    mma_gemm<128,128,32,1,true><<<dim3(18,32,1),256,S_QKV>>>(p);

    // QK^T per (b,h): S = Q K^T * 0.125 — single-stage BK=64
    p=GP{}; p.Ah=pq; p.Bh=pk;
    p.K=64; p.lda=64; p.ldb=64; p.sAz=65536; p.sBz=65536; p.sOz=HSs;
    p.o1=pS; p.ldo=1024; p.alpha=0.125f;
    mma_gemm<128,64,64,0,true><<<dim3(16,8,48),256,S_QK>>>(p);

    mixsoftmax<<<ROWS,512,SMIX>>>(pS,pP,t_before,t_after);

    // AV per (b,h): P[1024,1024] @ V[1024,64] (B row-major via trans-ldmatrix)
    p=GP{}; p.Ah=pP; p.Bh=pv;
    p.K=1024; p.lda=1024; p.ldb=64; p.sAz=HSs; p.sBz=65536;
    p.o1=pa;
    mma_gemm<64,64,32,2,false><<<dim3(1,16,48),256,S_AV>>>(p);

    // proj + bias + residual(x) -> x2
    p=GP{}; p.Ah=pa; p.Bh=w2;
    p.K=768; p.lda=768; p.ldb=768; p.bias=b_proj; p.res=x; p.outf=px2; p.ldo=768;
    mma_gemm<64,128,32,3,true><<<dim3(6,64,1),256,S_PRJ>>>(p);

    ln_kernel<<<ROWS,256>>>(px2,g2,be2,ph2,nullptr);
    dwln_kernel<<<ROWS,256>>>(ph2,dw_w,dw_b,gm,bm,pm);

    // fc1 + bias + gelu -> f
    p=GP{}; p.Ah=pm; p.Bh=w3;
    p.K=768; p.lda=768; p.ldb=768; p.bias=b_fc1; p.o1=pf; p.ldoh=3072;
    mma_gemm<128,128,32,4,true><<<dim3(24,32,1),256,S_FC1>>>(p);

    // fc2 + bias + residual(x2) -> out
    p=GP{}; p.Ah=pf; p.Bh=w4;
    p.K=3072; p.lda=3072; p.ldb=3072; p.bias=b_fc2; p.res=px2; p.outf=out; p.ldo=768;
    mma_gemm<64,128,32,3,true><<<dim3(6,64,1),256,S_PRJ>>>(p);
}

// round 14
// speedup vs baseline: 1.6337x; 1.0004x over previous
#include <cuda_runtime.h>
#include <cuda_fp16.h>
#include <math.h>
#include <stdint.h>
typedef __half hf;

#define NHEAD 12
#define ROWS  4096
#define HSs   1048576LL

// ---------------- scratch ----------------
__device__ __align__(16) hf    g_S  [50331648];
__device__ __align__(16) hf    g_P  [50331648];
__device__ __align__(16) hf    g_q  [3145728];
__device__ __align__(16) hf    g_k  [3145728];
__device__ __align__(16) hf    g_v  [3145728];
__device__ __align__(16) hf    g_h1 [3145728];
__device__ __align__(16) hf    g_a  [3145728];
__device__ __align__(16) hf    g_m  [3145728];
__device__ __align__(16) hf    g_f  [12582912];
__device__ __align__(16) float g_x2 [3145728], g_h2[3145728];
__device__ __align__(16) hf    g_w1 [1769472];
__device__ __align__(16) hf    g_w2 [589824];
__device__ __align__(16) hf    g_w3 [2359296];
__device__ __align__(16) hf    g_w4 [2359296];

__device__ __forceinline__ uint32_t smem_u32(const void* p){
    uint32_t a; asm("{ .reg .u64 t; cvta.to.shared.u64 t, %1; cvt.u32.u64 %0, t; }":"=r"(a):"l"(p)); return a;
}
#define LDM4(r0,r1,r2,r3,ad) asm volatile("ldmatrix.sync.aligned.m8n8.x4.shared.b16 {%0,%1,%2,%3},[%4];" \
    : "=r"(r0),"=r"(r1),"=r"(r2),"=r"(r3):"r"(ad))
#define LDM4T(r0,r1,r2,r3,ad) asm volatile("ldmatrix.sync.aligned.m8n8.x4.trans.shared.b16 {%0,%1,%2,%3},[%4];" \
    : "=r"(r0),"=r"(r1),"=r"(r2),"=r"(r3):"r"(ad))
#define MMA(d,a,b) asm volatile( \
    "mma.sync.aligned.m16n8k16.row.col.f32.f16.f16.f32 {%0,%1,%2,%3},{%4,%5,%6,%7},{%8,%9},{%0,%1,%2,%3};" \
    : "+f"((d)[0]),"+f"((d)[1]),"+f"((d)[2]),"+f"((d)[3]) \
    : "r"((a)[0]),"r"((a)[1]),"r"((a)[2]),"r"((a)[3]),"r"((b)[0]),"r"((b)[1]))
#define CPA(dst,src) asm volatile("cp.async.cg.shared.global [%0],[%1],16;"::"r"(dst),"l"(src))
#define CPCOMMIT()   asm volatile("cp.async.commit_group;":::"memory")
#define CPWAIT0()    asm volatile("cp.async.wait_group 0;":::"memory")
#define CPWAIT1()    asm volatile("cp.async.wait_group 1;":::"memory")

__device__ __forceinline__ void st_h2(hf* p, float a, float b){
    __half2 t; t.x=__float2half_rn(a); t.y=__float2half_rn(b); *(__half2*)p = t;
}

struct GP {
    const hf *Ah,*Bh;
    int K, lda, ldb;
    long long sAz, sBz, sOz;
    float alpha;
    const float *bias, *res;
    float *outf; int ldo;
    hf *o1; int ldoh;
    hf *kd,*vd;
};

// C[M,N] = A[M,K] @ op(B), single fp16 product.
// BT=true: B is [N,K] k-contig. BT=false: B is [K,N] n-contig (trans ldmatrix).
// 3-stage cp.async pipeline (degenerates gracefully for T==1).
// EPI: 0=alpha->fp16 batched, 1=QKV scatter, 2=AV->[B,N,C] fp16, 3=bias+res f32, 4=bias+gelu fp16
template<int BM,int BN,int BK,int EPI,bool BT>
__global__ void __launch_bounds__(256) mma_gemm(GP p){
    constexpr int WARPS_N = BN/32;
    constexpr int WARPS_M = 8/WARPS_N;
    constexpr int WM = BM/WARPS_M;
    constexpr int MT = WM/16;
    constexpr int APAD = BK+8;
    constexpr int BPAD = BT ? (BK+8) : (BN+8);
    constexpr int ABYT = BM*APAD*2;
    constexpr int BBYT = BT ? (BN*BPAD*2) : (BK*BPAD*2);
    constexpr int STG  = ABYT + BBYT;

    extern __shared__ char dsm[];
    const uint32_t sb = smem_u32(dsm);
    const int tid=threadIdx.x, wid=tid>>5, lane=tid&31;
    const int z=blockIdx.z, m0=blockIdx.y*BM, n0=blockIdx.x*BN;
    const int wm_=wid/WARPS_N, wn_=wid%WARPS_N;

    const hf* Ah=p.Ah+(long long)z*p.sAz;
    const hf* Bh=p.Bh+(long long)z*p.sBz;

    float acc[MT][4][4];
    #pragma unroll
    for(int i=0;i<MT;i++)
        #pragma unroll
        for(int j=0;j<4;j++)
            #pragma unroll
            for(int e=0;e<4;e++) acc[i][j][e]=0.f;

    auto load_stage=[&](int t,int s){
        const long long k0=(long long)t*BK;
        const uint32_t b0 = sb + s*STG;
        #pragma unroll
        for(int i=tid;i<BM*(BK/8);i+=256){
            int row=i/(BK/8), seg=i%(BK/8);
            uint32_t d = b0 + (row*APAD+seg*8)*2;
            long long g=(long long)(m0+row)*p.lda + k0 + seg*8;
            CPA(d, Ah+g);
        }
        if(BT){
            #pragma unroll
            for(int i=tid;i<BN*(BK/8);i+=256){
                int row=i/(BK/8), seg=i%(BK/8);
                uint32_t d=b0+ABYT+(row*BPAD+seg*8)*2;
                long long g=(long long)(n0+row)*p.ldb + k0 + seg*8;
                CPA(d, Bh+g);
            }
        } else {
            #pragma unroll
            for(int i=tid;i<BK*(BN/8);i+=256){
                int row=i/(BN/8), seg=i%(BN/8);
                uint32_t d=b0+ABYT+(row*BPAD+seg*8)*2;
                long long g=(long long)(k0+row)*p.ldb + n0 + seg*8;
                CPA(d, Bh+g);
            }
        }
        CPCOMMIT();
    };

    auto compute=[&](int s){
        const uint32_t bA=sb+s*STG, bB=bA+ABYT;
        #pragma unroll
        for(int kk=0;kk<BK;kk+=16){
            uint32_t bh[4][2];
            #pragma unroll
            for(int nt=0;nt<2;nt++){
                if(BT){
                    int row = wn_*32 + nt*16 + (lane&7) + ((lane>>4)&1)*8;
                    int ko  = kk + ((lane>>3)&1)*8;
                    uint32_t off=(uint32_t)(row*BPAD+ko)*2;
                    LDM4(bh[2*nt][0],bh[2*nt][1],bh[2*nt+1][0],bh[2*nt+1][1], bB+off);
                } else {
                    int kb = kk + (lane&7) + ((lane>>3)&1)*8;
                    int nb = wn_*32 + nt*16 + ((lane>>4)&1)*8;
                    uint32_t off=(uint32_t)(kb*BPAD+nb)*2;
                    LDM4T(bh[2*nt][0],bh[2*nt][1],bh[2*nt+1][0],bh[2*nt+1][1], bB+off);
                }
            }
            #pragma unroll
            for(int mi=0;mi<MT;mi++){
                int row = wm_*WM + mi*16 + (lane&7) + ((lane>>3)&1)*8;
                int ko  = kk + ((lane>>4)&1)*8;
                uint32_t off=(uint32_t)(row*APAD+ko)*2;
                uint32_t ah[4];
                LDM4(ah[0],ah[1],ah[2],ah[3], bA+off);
                #pragma unroll
                for(int ni=0;ni<4;ni++) MMA(acc[mi][ni],ah,bh[ni]);
            }
        }
    };

    const int T = p.K/BK;
    load_stage(0,0);
    if(T>1) load_stage(1,1);
    for(int t=0;t<T;t++){
        if(t+1<T){ CPWAIT1(); } else { CPWAIT0(); }
        __syncthreads();
        if(t+2<T) load_stage(t+2,(t+2)%3);
        compute(t%3);
    }

    // -------- epilogue --------
    const int rb = m0 + wm_*WM, cbse = n0 + wn_*32;
    #pragma unroll
    for(int mi=0;mi<MT;mi++){
        #pragma unroll
        for(int ni=0;ni<4;ni++){
            #pragma unroll
            for(int half=0;half<2;half++){
                int r = rb + mi*16 + (lane>>2) + half*8;
                int c = cbse + ni*8 + (lane&3)*2;
                float v0=acc[mi][ni][half*2], v1=acc[mi][ni][half*2+1];
                if(EPI==0){
                    st_h2(p.o1 + (long long)z*p.sOz + (long long)r*p.ldo + c,
                          v0*p.alpha, v1*p.alpha);
                } else if(EPI==1){
                    v0+=p.bias[c]; v1+=p.bias[c+1];
                    int b=r>>10, n=r&1023;
                    hf* dst = (c<768)?p.o1 : ((c<1536)?p.kd:p.vd);
                    int cc  = (c<768)?c   : ((c<1536)?c-768:c-1536);
                    int hh=cc>>6, d=cc&63;
                    long long o=((long long)(b*12+hh)*1024+n)*64+d;
                    st_h2(dst+o, v0, v1);
                } else if(EPI==2){
                    int b=z/12, hh=z-b*12;
                    long long o=(long long)(b*1024+r)*768 + hh*64 + c;
                    st_h2(p.o1+o, v0, v1);
                } else if(EPI==3){
                    long long o=(long long)r*p.ldo + c;
                    float2 rr=*(const float2*)(p.res+o);
                    float2 ov; ov.x=v0+p.bias[c]+rr.x; ov.y=v1+p.bias[c+1]+rr.y;
                    *(float2*)(p.outf+o)=ov;
                } else if(EPI==4){
                    v0+=p.bias[c]; v1+=p.bias[c+1];
                    v0=0.5f*v0*(1.0f+erff(v0*0.70710678118654752f));
                    v1=0.5f*v1*(1.0f+erff(v1*0.70710678118654752f));
                    st_h2(p.o1+(long long)r*p.ldoh+c, v0, v1);
                }
            }
        }
    }
}

// ---------------- LayerNorm body (callable) ----------------
__device__ __forceinline__ void ln_body(const float* x, const float* g, const float* b,
                                        float* outf, hf* oh, long long row, int tid){
    float xv[3], s=0.f, ss=0.f;
    #pragma unroll
    for(int i=0;i<3;i++){ float v=x[tid+i*256]; xv[i]=v; s+=v; ss+=v*v; }
    __shared__ float red[64];
    #pragma unroll
    for(int o=16;o>0;o>>=1){ s+=__shfl_down_sync(~0u,s,o); ss+=__shfl_down_sync(~0u,ss,o); }
    int warp=tid>>5, lane=tid&31;
    if(lane==0){ red[warp]=s; red[32+warp]=ss; }
    __syncthreads();
    if(warp==0){
        s=(lane<8)?red[lane]:0.f; ss=(lane<8)?red[32+lane]:0.f;
        #pragma unroll
        for(int o=4;o>0;o>>=1){ s+=__shfl_down_sync(~0u,s,o); ss+=__shfl_down_sync(~0u,ss,o); }
        if(lane==0){ red[0]=s; red[1]=ss; }
    }
    __syncthreads();
    float mu=red[0]*(1.f/768), var=red[1]*(1.f/768)-mu*mu, rstd=rsqrtf(var+1e-5f);
    #pragma unroll
    for(int i=0;i<3;i++){
        int c=tid+i*256;
        float v=(xv[i]-mu)*rstd*g[c]+b[c];
        long long o=row*768+c;
        if(outf) outf[o]=v;
        if(oh) oh[o]=__float2half_rn(v);
    }
}

__global__ void ln_kernel(const float* __restrict__ in, const float* __restrict__ g,
                          const float* __restrict__ b, float* __restrict__ outf,
                          hf* __restrict__ oh){
    ln_body(in + (long long)blockIdx.x*768, g, b, outf, oh, blockIdx.x, threadIdx.x);
}

// ---------------- fused wconv + ln1 ----------------
__global__ void pre_kernel(const float* __restrict__ x, const float* __restrict__ g1,
                           const float* __restrict__ be1, hf* __restrict__ oh,
                           const float* __restrict__ w1,const float* __restrict__ w2,
                           const float* __restrict__ w3,const float* __restrict__ w4,
                           hf* o1,hf* o2,hf* o3,hf* o4){
    int bid=blockIdx.x;
    if(bid<4096){
        ln_body(x + (long long)bid*768, g1, be1, nullptr, oh, bid, threadIdx.x);
    } else {
        int i=(bid-4096)*256+threadIdx.x;
        const float* s; hf *ohw; int j=i;
        if(j<1769472){ s=w1; ohw=o1; }
        else if((j-=1769472)<589824){ s=w2; ohw=o2; }
        else if((j-=589824)<2359296){ s=w3; ohw=o3; }
        else { j-=2359296; s=w4; ohw=o4; }
        ohw[j]=__float2half_rn(s[j]);
    }
}

// ---------------- fused mix->softmax->mix: 512 threads, e kept in registers ----------------
__global__ void __launch_bounds__(512) mixsoftmax(
    const hf* __restrict__ S, hf* __restrict__ P,
    const float* __restrict__ tb, const float* __restrict__ ta){
    __shared__ float tbs[144], tas[144], wsum[16][12], rin[12];
    int tid=threadIdx.x, warp=tid>>5, lane=tid&31;
    if(tid<144){ tbs[tid]=tb[tid]; tas[tid]=ta[tid]; }
    __syncthreads();
    int bn=blockIdx.x, b=bn>>10, n=bn&1023;
    long long base=((long long)b*NHEAD*1024+n)*1024;
    const __half2* Sb=(const __half2*)(S+base);
    __half2* Pb=(__half2*)(P+base);
    const int mp=tid;                                // one half2 column per thread
    __half2 eh[12];                                  // e-values live in registers
    float sm[12];
    {
        float2 s[12];
        #pragma unroll
        for(int h=0;h<12;h++) s[h]=__half22float2(Sb[(uint32_t)(h*524288)+mp]);
        #pragma unroll
        for(int g=0;g<12;g++){
            float v0=0.f, v1=0.f;
            #pragma unroll
            for(int h=0;h<12;h++){ v0=fmaf(tbs[g*12+h],s[h].x,v0); v1=fmaf(tbs[g*12+h],s[h].y,v1); }
            float e0=__expf(v0), e1=__expf(v1);
            eh[g]=__floats2half2_rn(e0,e1);
            sm[g]=e0+e1;
        }
    }
    #pragma unroll
    for(int o=16;o>0;o>>=1){
        #pragma unroll
        for(int g=0;g<12;g++) sm[g]+=__shfl_xor_sync(~0u,sm[g],o);
    }
    if(lane==0){
        #pragma unroll
        for(int g=0;g<12;g++) wsum[warp][g]=sm[g];
    }
    __syncthreads();
    if(tid<12){
        float t=0.f;
        #pragma unroll
        for(int w=0;w<16;w++) t+=wsum[w][tid];
        rin[tid]=1.f/t;
    }
    __syncthreads();
    {
        float2 e[12];
        #pragma unroll
        for(int h=0;h<12;h++){
            e[h]=__half22float2(eh[h]);
            float r=rin[h];
            e[h].x*=r; e[h].y*=r;
        }
        #pragma unroll
        for(int g=0;g<12;g++){
            float v0=0.f, v1=0.f;
            #pragma unroll
            for(int h=0;h<12;h++){ v0=fmaf(tas[g*12+h],e[h].x,v0); v1=fmaf(tas[g*12+h],e[h].y,v1); }
            Pb[(uint32_t)(g*524288)+mp]=__floats2half2_rn(v0,v1);
        }
    }
}

// ---------------- fused depthwise conv + LN(gm,bm) ----------------
__global__ void dwln_kernel(const float* __restrict__ in, const float* __restrict__ w,
                            const float* __restrict__ bias, const float* __restrict__ gm,
                            const float* __restrict__ bm, hf* __restrict__ om){
    int row=blockIdx.x, tid=threadIdx.x;
    int b=row>>10, n=row&1023;
    const float* xp = in + (long long)b*1024*768;
    float acc[3], s=0.f, ss=0.f;
    #pragma unroll
    for(int i=0;i<3;i++){
        int c=tid+i*256;
        float a=bias[c];
        #pragma unroll
        for(int k=0;k<7;k++){
            int m=n+k-3;
            if(m>=0 && m<1024) a+=w[c*7+k]*xp[(long long)m*768+c];
        }
        acc[i]=a; s+=a; ss+=a*a;
    }
    __shared__ float red[64];
    #pragma unroll
    for(int o=16;o>0;o>>=1){ s+=__shfl_down_sync(~0u,s,o); ss+=__shfl_down_sync(~0u,ss,o); }
    int warp=tid>>5, lane=tid&31;
    if(lane==0){ red[warp]=s; red[32+warp]=ss; }
    __syncthreads();
    if(warp==0){
        s=(lane<8)?red[lane]:0.f; ss=(lane<8)?red[32+lane]:0.f;
        #pragma unroll
        for(int o=4;o>0;o>>=1){ s+=__shfl_down_sync(~0u,s,o); ss+=__shfl_down_sync(~0u,ss,o); }
        if(lane==0){ red[0]=s; red[1]=ss; }
    }
    __syncthreads();
    float mu=red[0]*(1.f/768), var=red[1]*(1.f/768)-mu*mu, rstd=rsqrtf(var+1e-5f);
    #pragma unroll
    for(int i=0;i<3;i++){
        int c=tid+i*256;
        om[(long long)row*768+c]=__float2half_rn((acc[i]-mu)*rstd*gm[c]+bm[c]);
    }
}

// ---------------- launch ----------------
extern "C" void kernel_launch(void* const* d_in, const int* in_sizes, int n_in,
                              void* d_out, int out_size){
    const float *x=(const float*)d_in[0], *w_qkv=(const float*)d_in[1], *b_qkv=(const float*)d_in[2];
    const float *w_proj=(const float*)d_in[3], *b_proj=(const float*)d_in[4];
    const float *w_fc1=(const float*)d_in[5], *b_fc1=(const float*)d_in[6];
    const float *w_fc2=(const float*)d_in[7], *b_fc2=(const float*)d_in[8];
    const float *t_before=(const float*)d_in[9], *t_after=(const float*)d_in[10];
    const float *g1=(const float*)d_in[11], *be1=(const float*)d_in[12];
    const float *g2=(const float*)d_in[13], *be2=(const float*)d_in[14];
    const float *dw_w=(const float*)d_in[15], *dw_b=(const float*)d_in[16];
    const float *gm=(const float*)d_in[17], *bm=(const float*)d_in[18];
    float* out=(float*)d_out;

    float *px2,*ph2;
    hf *pS,*pP,*pq,*pk,*pv,*ph1,*pa,*pm,*pf,*w1,*w2,*w3,*w4;
    cudaGetSymbolAddress((void**)&pS,g_S);   cudaGetSymbolAddress((void**)&px2,g_x2);
    cudaGetSymbolAddress((void**)&ph2,g_h2);
    cudaGetSymbolAddress((void**)&pP,g_P);   cudaGetSymbolAddress((void**)&pq,g_q);
    cudaGetSymbolAddress((void**)&pk,g_k);   cudaGetSymbolAddress((void**)&pv,g_v);
    cudaGetSymbolAddress((void**)&ph1,g_h1); cudaGetSymbolAddress((void**)&pa,g_a);
    cudaGetSymbolAddress((void**)&pm,g_m);   cudaGetSymbolAddress((void**)&pf,g_f);
    cudaGetSymbolAddress((void**)&w1,g_w1);  cudaGetSymbolAddress((void**)&w2,g_w2);
    cudaGetSymbolAddress((void**)&w3,g_w3);  cudaGetSymbolAddress((void**)&w4,g_w4);

    // smem sizes
    const int S_QKV = 3*((128*40 + 128*40)*2);          // 61440
    const int S_QK  = 1*((128*72 + 64*72)*2);           // 27648
    const int S_AV  = 3*((64*40)*2 + (32*72)*2);        // 29184
    const int S_PRJ = 3*((64*40 + 128*40)*2);           // 46080
    const int S_FC1 = 3*((128*40 + 128*40)*2);          // 61440
    cudaFuncSetAttribute(mma_gemm<128,128,32,1,true>, cudaFuncAttributeMaxDynamicSharedMemorySize, S_QKV);
    cudaFuncSetAttribute(mma_gemm<128,64,64,0,true>,  cudaFuncAttributeMaxDynamicSharedMemorySize, S_QK);
    cudaFuncSetAttribute(mma_gemm<64,64,32,2,false>,  cudaFuncAttributeMaxDynamicSharedMemorySize, S_AV);
    cudaFuncSetAttribute(mma_gemm<64,128,32,3,true>,  cudaFuncAttributeMaxDynamicSharedMemorySize, S_PRJ);
    cudaFuncSetAttribute(mma_gemm<128,128,32,4,true>, cudaFuncAttributeMaxDynamicSharedMemorySize, S_FC1);

    // fused ln1 + weight convert
    pre_kernel<<<4096+27648,256>>>(x,g1,be1,ph1, w_qkv,w_proj,w_fc1,w_fc2, w1,w2,w3,w4);

    GP p{};
    // QKV: h1 @ w_qkv^T + b -> q, k, v
    p.Ah=ph1; p.Bh=w1; p.K=768; p.lda=768; p.ldb=768;
    p.bias=b_qkv; p.o1=pq; p.kd=pk; p.vd=pv;
    mma_gemm<128,128,32,1,true><<<dim3(18,32,1),256,S_QKV>>>(p);

    // QK^T per (b,h): S = Q K^T * 0.125 — single-stage BK=64
    p=GP{}; p.Ah=pq; p.Bh=pk;
    p.K=64; p.lda=64; p.ldb=64; p.sAz=65536; p.sBz=65536; p.sOz=HSs;
    p.o1=pS; p.ldo=1024; p.alpha=0.125f;
    mma_gemm<128,64,64,0,true><<<dim3(16,8,48),256,S_QK>>>(p);

    mixsoftmax<<<ROWS,512>>>(pS,pP,t_before,t_after);

    // AV per (b,h): P[1024,1024] @ V[1024,64] (B row-major via trans-ldmatrix)
    p=GP{}; p.Ah=pP; p.Bh=pv;
    p.K=1024; p.lda=1024; p.ldb=64; p.sAz=HSs; p.sBz=65536;
    p.o1=pa;
    mma_gemm<64,64,32,2,false><<<dim3(1,16,48),256,S_AV>>>(p);

    // proj + bias + residual(x) -> x2
    p=GP{}; p.Ah=pa; p.Bh=w2;
    p.K=768; p.lda=768; p.ldb=768; p.bias=b_proj; p.res=x; p.outf=px2; p.ldo=768;
    mma_gemm<64,128,32,3,true><<<dim3(6,64,1),256,S_PRJ>>>(p);

    ln_kernel<<<ROWS,256>>>(px2,g2,be2,ph2,nullptr);
    dwln_kernel<<<ROWS,256>>>(ph2,dw_w,dw_b,gm,bm,pm);

    // fc1 + bias + gelu -> f
    p=GP{}; p.Ah=pm; p.Bh=w3;
    p.K=768; p.lda=768; p.ldb=768; p.bias=b_fc1; p.o1=pf; p.ldoh=3072;
    mma_gemm<128,128,32,4,true><<<dim3(24,32,1),256,S_FC1>>>(p);

    // fc2 + bias + residual(x2) -> out
    p=GP{}; p.Ah=pf; p.Bh=w4;
    p.K=3072; p.lda=3072; p.ldb=3072; p.bias=b_fc2; p.res=px2; p.outf=out; p.ldo=768;
    mma_gemm<64,128,32,3,true><<<dim3(6,64,1),256,S_PRJ>>>(p);
}

// round 15
// speedup vs baseline: 1.6756x; 1.0257x over previous
#include <cuda_runtime.h>
#include <cuda_fp16.h>
#include <math.h>
#include <stdint.h>
typedef __half hf;

#define NHEAD 12
#define ROWS  4096
#define HSs   1048576LL

// ---------------- scratch ----------------
__device__ __align__(16) hf    g_S  [50331648];
__device__ __align__(16) hf    g_P  [50331648];
__device__ __align__(16) hf    g_q  [3145728];
__device__ __align__(16) hf    g_k  [3145728];
__device__ __align__(16) hf    g_v  [3145728];
__device__ __align__(16) hf    g_h1 [3145728];
__device__ __align__(16) hf    g_a  [3145728];
__device__ __align__(16) hf    g_m  [3145728];
__device__ __align__(16) hf    g_f  [12582912];
__device__ __align__(16) float g_x2 [3145728], g_h2[3145728];
__device__ __align__(16) hf    g_w1 [1769472];
__device__ __align__(16) hf    g_w2 [589824];
__device__ __align__(16) hf    g_w3 [2359296];
__device__ __align__(16) hf    g_w4 [2359296];

__device__ __forceinline__ uint32_t smem_u32(const void* p){
    uint32_t a; asm("{ .reg .u64 t; cvta.to.shared.u64 t, %1; cvt.u32.u64 %0, t; }":"=r"(a):"l"(p)); return a;
}
#define LDM4(r0,r1,r2,r3,ad) asm volatile("ldmatrix.sync.aligned.m8n8.x4.shared.b16 {%0,%1,%2,%3},[%4];" \
    : "=r"(r0),"=r"(r1),"=r"(r2),"=r"(r3):"r"(ad))
#define LDM4T(r0,r1,r2,r3,ad) asm volatile("ldmatrix.sync.aligned.m8n8.x4.trans.shared.b16 {%0,%1,%2,%3},[%4];" \
    : "=r"(r0),"=r"(r1),"=r"(r2),"=r"(r3):"r"(ad))
#define MMA(d,a,b) asm volatile( \
    "mma.sync.aligned.m16n8k16.row.col.f32.f16.f16.f32 {%0,%1,%2,%3},{%4,%5,%6,%7},{%8,%9},{%0,%1,%2,%3};" \
    : "+f"((d)[0]),"+f"((d)[1]),"+f"((d)[2]),"+f"((d)[3]) \
    : "r"((a)[0]),"r"((a)[1]),"r"((a)[2]),"r"((a)[3]),"r"((b)[0]),"r"((b)[1]))
#define CPA(dst,src) asm volatile("cp.async.cg.shared.global [%0],[%1],16;"::"r"(dst),"l"(src))
#define CPCOMMIT()   asm volatile("cp.async.commit_group;":::"memory")
#define CPWAIT0()    asm volatile("cp.async.wait_group 0;":::"memory")
#define CPWAIT1()    asm volatile("cp.async.wait_group 1;":::"memory")

__device__ __forceinline__ void st_h2(hf* p, float a, float b){
    __half2 t; t.x=__float2half_rn(a); t.y=__float2half_rn(b); *(__half2*)p = t;
}

struct GP {
    const hf *Ah,*Bh;
    int K, lda, ldb;
    long long sAz, sBz, sOz;
    float alpha;
    const float *bias, *res;
    float *outf; int ldo;
    hf *o1; int ldoh;
    hf *kd,*vd;
};

// C[M,N] = A[M,K] @ op(B), single fp16 product.
// BT=true: B is [N,K] k-contig. BT=false: B is [K,N] n-contig (trans ldmatrix).
// 3-stage cp.async pipeline (degenerates gracefully for T==1).
// EPI: 0=alpha->fp16 batched, 1=QKV scatter, 2=AV->[B,N,C] fp16, 3=bias+res f32, 4=bias+gelu fp16
template<int BM,int BN,int BK,int EPI,bool BT>
__global__ void __launch_bounds__(256) mma_gemm(GP p){
    constexpr int WARPS_N = BN/32;
    constexpr int WARPS_M = 8/WARPS_N;
    constexpr int WM = BM/WARPS_M;
    constexpr int MT = WM/16;
    constexpr int APAD = BK+8;
    constexpr int BPAD = BT ? (BK+8) : (BN+8);
    constexpr int ABYT = BM*APAD*2;
    constexpr int BBYT = BT ? (BN*BPAD*2) : (BK*BPAD*2);
    constexpr int STG  = ABYT + BBYT;

    extern __shared__ char dsm[];
    const uint32_t sb = smem_u32(dsm);
    const int tid=threadIdx.x, wid=tid>>5, lane=tid&31;
    const int z=blockIdx.z, m0=blockIdx.y*BM, n0=blockIdx.x*BN;
    const int wm_=wid/WARPS_N, wn_=wid%WARPS_N;

    const hf* Ah=p.Ah+(long long)z*p.sAz;
    const hf* Bh=p.Bh+(long long)z*p.sBz;

    float acc[MT][4][4];
    #pragma unroll
    for(int i=0;i<MT;i++)
        #pragma unroll
        for(int j=0;j<4;j++)
            #pragma unroll
            for(int e=0;e<4;e++) acc[i][j][e]=0.f;

    auto load_stage=[&](int t,int s){
        const long long k0=(long long)t*BK;
        const uint32_t b0 = sb + s*STG;
        #pragma unroll
        for(int i=tid;i<BM*(BK/8);i+=256){
            int row=i/(BK/8), seg=i%(BK/8);
            uint32_t d = b0 + (row*APAD+seg*8)*2;
            long long g=(long long)(m0+row)*p.lda + k0 + seg*8;
            CPA(d, Ah+g);
        }
        if(BT){
            #pragma unroll
            for(int i=tid;i<BN*(BK/8);i+=256){
                int row=i/(BK/8), seg=i%(BK/8);
                uint32_t d=b0+ABYT+(row*BPAD+seg*8)*2;
                long long g=(long long)(n0+row)*p.ldb + k0 + seg*8;
                CPA(d, Bh+g);
            }
        } else {
            #pragma unroll
            for(int i=tid;i<BK*(BN/8);i+=256){
                int row=i/(BN/8), seg=i%(BN/8);
                uint32_t d=b0+ABYT+(row*BPAD+seg*8)*2;
                long long g=(long long)(k0+row)*p.ldb + n0 + seg*8;
                CPA(d, Bh+g);
            }
        }
        CPCOMMIT();
    };

    auto compute=[&](int s){
        const uint32_t bA=sb+s*STG, bB=bA+ABYT;
        #pragma unroll
        for(int kk=0;kk<BK;kk+=16){
            uint32_t bh[4][2];
            #pragma unroll
            for(int nt=0;nt<2;nt++){
                if(BT){
                    int row = wn_*32 + nt*16 + (lane&7) + ((lane>>4)&1)*8;
                    int ko  = kk + ((lane>>3)&1)*8;
                    uint32_t off=(uint32_t)(row*BPAD+ko)*2;
                    LDM4(bh[2*nt][0],bh[2*nt][1],bh[2*nt+1][0],bh[2*nt+1][1], bB+off);
                } else {
                    int kb = kk + (lane&7) + ((lane>>3)&1)*8;
                    int nb = wn_*32 + nt*16 + ((lane>>4)&1)*8;
                    uint32_t off=(uint32_t)(kb*BPAD+nb)*2;
                    LDM4T(bh[2*nt][0],bh[2*nt][1],bh[2*nt+1][0],bh[2*nt+1][1], bB+off);
                }
            }
            #pragma unroll
            for(int mi=0;mi<MT;mi++){
                int row = wm_*WM + mi*16 + (lane&7) + ((lane>>3)&1)*8;
                int ko  = kk + ((lane>>4)&1)*8;
                uint32_t off=(uint32_t)(row*APAD+ko)*2;
                uint32_t ah[4];
                LDM4(ah[0],ah[1],ah[2],ah[3], bA+off);
                #pragma unroll
                for(int ni=0;ni<4;ni++) MMA(acc[mi][ni],ah,bh[ni]);
            }
        }
    };

    const int T = p.K/BK;
    load_stage(0,0);
    if(T>1) load_stage(1,1);
    for(int t=0;t<T;t++){
        if(t+1<T){ CPWAIT1(); } else { CPWAIT0(); }
        __syncthreads();
        if(t+2<T) load_stage(t+2,(t+2)%3);
        compute(t%3);
    }

    // -------- epilogue --------
    const int rb = m0 + wm_*WM, cbse = n0 + wn_*32;
    #pragma unroll
    for(int mi=0;mi<MT;mi++){
        #pragma unroll
        for(int ni=0;ni<4;ni++){
            #pragma unroll
            for(int half=0;half<2;half++){
                int r = rb + mi*16 + (lane>>2) + half*8;
                int c = cbse + ni*8 + (lane&3)*2;
                float v0=acc[mi][ni][half*2], v1=acc[mi][ni][half*2+1];
                if(EPI==0){
                    st_h2(p.o1 + (long long)z*p.sOz + (long long)r*p.ldo + c,
                          v0*p.alpha, v1*p.alpha);
                } else if(EPI==1){
                    v0+=p.bias[c]; v1+=p.bias[c+1];
                    int b=r>>10, n=r&1023;
                    hf* dst = (c<768)?p.o1 : ((c<1536)?p.kd:p.vd);
                    int cc  = (c<768)?c   : ((c<1536)?c-768:c-1536);
                    int hh=cc>>6, d=cc&63;
                    long long o=((long long)(b*12+hh)*1024+n)*64+d;
                    st_h2(dst+o, v0, v1);
                } else if(EPI==2){
                    int b=z/12, hh=z-b*12;
                    long long o=(long long)(b*1024+r)*768 + hh*64 + c;
                    st_h2(p.o1+o, v0, v1);
                } else if(EPI==3){
                    long long o=(long long)r*p.ldo + c;
                    float2 rr=*(const float2*)(p.res+o);
                    float2 ov; ov.x=v0+p.bias[c]+rr.x; ov.y=v1+p.bias[c+1]+rr.y;
                    *(float2*)(p.outf+o)=ov;
                } else if(EPI==4){
                    v0+=p.bias[c]; v1+=p.bias[c+1];
                    v0=0.5f*v0*(1.0f+erff(v0*0.70710678118654752f));
                    v1=0.5f*v1*(1.0f+erff(v1*0.70710678118654752f));
                    st_h2(p.o1+(long long)r*p.ldoh+c, v0, v1);
                }
            }
        }
    }
}

// ---------------- LayerNorm body (callable) ----------------
__device__ __forceinline__ void ln_body(const float* x, const float* g, const float* b,
                                        float* outf, hf* oh, long long row, int tid){
    float xv[3], s=0.f, ss=0.f;
    #pragma unroll
    for(int i=0;i<3;i++){ float v=x[tid+i*256]; xv[i]=v; s+=v; ss+=v*v; }
    __shared__ float red[64];
    #pragma unroll
    for(int o=16;o>0;o>>=1){ s+=__shfl_down_sync(~0u,s,o); ss+=__shfl_down_sync(~0u,ss,o); }
    int warp=tid>>5, lane=tid&31;
    if(lane==0){ red[warp]=s; red[32+warp]=ss; }
    __syncthreads();
    if(warp==0){
        s=(lane<8)?red[lane]:0.f; ss=(lane<8)?red[32+lane]:0.f;
        #pragma unroll
        for(int o=4;o>0;o>>=1){ s+=__shfl_down_sync(~0u,s,o); ss+=__shfl_down_sync(~0u,ss,o); }
        if(lane==0){ red[0]=s; red[1]=ss; }
    }
    __syncthreads();
    float mu=red[0]*(1.f/768), var=red[1]*(1.f/768)-mu*mu, rstd=rsqrtf(var+1e-5f);
    #pragma unroll
    for(int i=0;i<3;i++){
        int c=tid+i*256;
        float v=(xv[i]-mu)*rstd*g[c]+b[c];
        long long o=row*768+c;
        if(outf) outf[o]=v;
        if(oh) oh[o]=__float2half_rn(v);
    }
}

__global__ void ln_kernel(const float* __restrict__ in, const float* __restrict__ g,
                          const float* __restrict__ b, float* __restrict__ outf,
                          hf* __restrict__ oh){
    ln_body(in + (long long)blockIdx.x*768, g, b, outf, oh, blockIdx.x, threadIdx.x);
}

// ---------------- fused wconv + ln1 ----------------
__global__ void pre_kernel(const float* __restrict__ x, const float* __restrict__ g1,
                           const float* __restrict__ be1, hf* __restrict__ oh,
                           const float* __restrict__ w1,const float* __restrict__ w2,
                           const float* __restrict__ w3,const float* __restrict__ w4,
                           hf* o1,hf* o2,hf* o3,hf* o4){
    int bid=blockIdx.x;
    if(bid<4096){
        ln_body(x + (long long)bid*768, g1, be1, nullptr, oh, bid, threadIdx.x);
    } else {
        int i=(bid-4096)*256+threadIdx.x;
        const float* s; hf *ohw; int j=i;
        if(j<1769472){ s=w1; ohw=o1; }
        else if((j-=1769472)<589824){ s=w2; ohw=o2; }
        else if((j-=589824)<2359296){ s=w3; ohw=o3; }
        else { j-=2359296; s=w4; ohw=o4; }
        ohw[j]=__float2half_rn(s[j]);
    }
}

// ---------------- fused mix->softmax->mix: HFMA2 mixing, fp32 normalizer ----------------
__global__ void __launch_bounds__(512) mixsoftmax(
    const hf* __restrict__ S, hf* __restrict__ P,
    const float* __restrict__ tb, const float* __restrict__ ta){
    __shared__ __half2 tbs2[144], tas2[144];
    __shared__ float wsum[16][12], rin[12];
    int tid=threadIdx.x, warp=tid>>5, lane=tid&31;
    if(tid<144){ tbs2[tid]=__float2half2_rn(tb[tid]); tas2[tid]=__float2half2_rn(ta[tid]); }
    __syncthreads();
    int bn=blockIdx.x, b=bn>>10, n=bn&1023;
    long long base=((long long)b*NHEAD*1024+n)*1024;
    const __half2* Sb=(const __half2*)(S+base);
    __half2* Pb=(__half2*)(P+base);
    const int mp=tid;
    __half2 eh[12];
    float sm[12];
    {
        __half2 s2[12];
        #pragma unroll
        for(int h=0;h<12;h++) s2[h]=Sb[(uint32_t)(h*524288)+mp];
        #pragma unroll
        for(int g=0;g<12;g++){
            __half2 v=__float2half2_rn(0.f);
            #pragma unroll
            for(int h=0;h<12;h++) v=__hfma2(tbs2[g*12+h],s2[h],v);
            __half2 e=h2exp(v);
            eh[g]=e;
            float2 ef=__half22float2(e);
            sm[g]=ef.x+ef.y;
        }
    }
    #pragma unroll
    for(int o=16;o>0;o>>=1){
        #pragma unroll
        for(int g=0;g<12;g++) sm[g]+=__shfl_xor_sync(~0u,sm[g],o);
    }
    if(lane==0){
        #pragma unroll
        for(int g=0;g<12;g++) wsum[warp][g]=sm[g];
    }
    __syncthreads();
    if(tid<12){
        float t=0.f;
        #pragma unroll
        for(int w=0;w<16;w++) t+=wsum[w][tid];
        rin[tid]=1.f/t;
    }
    __syncthreads();
    {
        __half2 ep[12];
        #pragma unroll
        for(int h=0;h<12;h++) ep[h]=__hmul2(eh[h],__float2half2_rn(rin[h]));
        #pragma unroll
        for(int g=0;g<12;g++){
            __half2 v=__float2half2_rn(0.f);
            #pragma unroll
            for(int h=0;h<12;h++) v=__hfma2(tas2[g*12+h],ep[h],v);
            Pb[(uint32_t)(g*524288)+mp]=v;
        }
    }
}

// ---------------- fused depthwise conv + LN(gm,bm) ----------------
__global__ void dwln_kernel(const float* __restrict__ in, const float* __restrict__ w,
                            const float* __restrict__ bias, const float* __restrict__ gm,
                            const float* __restrict__ bm, hf* __restrict__ om){
    int row=blockIdx.x, tid=threadIdx.x;
    int b=row>>10, n=row&1023;
    const float* xp = in + (long long)b*1024*768;
    float acc[3], s=0.f, ss=0.f;
    #pragma unroll
    for(int i=0;i<3;i++){
        int c=tid+i*256;
        float a=bias[c];
        #pragma unroll
        for(int k=0;k<7;k++){
            int m=n+k-3;
            if(m>=0 && m<1024) a+=w[c*7+k]*xp[(long long)m*768+c];
        }
        acc[i]=a; s+=a; ss+=a*a;
    }
    __shared__ float red[64];
    #pragma unroll
    for(int o=16;o>0;o>>=1){ s+=__shfl_down_sync(~0u,s,o); ss+=__shfl_down_sync(~0u,ss,o); }
    int warp=tid>>5, lane=tid&31;
    if(lane==0){ red[warp]=s; red[32+warp]=ss; }
    __syncthreads();
    if(warp==0){
        s=(lane<8)?red[lane]:0.f; ss=(lane<8)?red[32+lane]:0.f;
        #pragma unroll
        for(int o=4;o>0;o>>=1){ s+=__shfl_down_sync(~0u,s,o); ss+=__shfl_down_sync(~0u,ss,o); }
        if(lane==0){ red[0]=s; red[1]=ss; }
    }
    __syncthreads();
    float mu=red[0]*(1.f/768), var=red[1]*(1.f/768)-mu*mu, rstd=rsqrtf(var+1e-5f);
    #pragma unroll
    for(int i=0;i<3;i++){
        int c=tid+i*256;
        om[(long long)row*768+c]=__float2half_rn((acc[i]-mu)*rstd*gm[c]+bm[c]);
    }
}

// ---------------- launch ----------------
extern "C" void kernel_launch(void* const* d_in, const int* in_sizes, int n_in,
                              void* d_out, int out_size){
    const float *x=(const float*)d_in[0], *w_qkv=(const float*)d_in[1], *b_qkv=(const float*)d_in[2];
    const float *w_proj=(const float*)d_in[3], *b_proj=(const float*)d_in[4];
    const float *w_fc1=(const float*)d_in[5], *b_fc1=(const float*)d_in[6];
    const float *w_fc2=(const float*)d_in[7], *b_fc2=(const float*)d_in[8];
    const float *t_before=(const float*)d_in[9], *t_after=(const float*)d_in[10];
    const float *g1=(const float*)d_in[11], *be1=(const float*)d_in[12];
    const float *g2=(const float*)d_in[13], *be2=(const float*)d_in[14];
    const float *dw_w=(const float*)d_in[15], *dw_b=(const float*)d_in[16];
    const float *gm=(const float*)d_in[17], *bm=(const float*)d_in[18];
    float* out=(float*)d_out;

    float *px2,*ph2;
    hf *pS,*pP,*pq,*pk,*pv,*ph1,*pa,*pm,*pf,*w1,*w2,*w3,*w4;
    cudaGetSymbolAddress((void**)&pS,g_S);   cudaGetSymbolAddress((void**)&px2,g_x2);
    cudaGetSymbolAddress((void**)&ph2,g_h2);
    cudaGetSymbolAddress((void**)&pP,g_P);   cudaGetSymbolAddress((void**)&pq,g_q);
    cudaGetSymbolAddress((void**)&pk,g_k);   cudaGetSymbolAddress((void**)&pv,g_v);
    cudaGetSymbolAddress((void**)&ph1,g_h1); cudaGetSymbolAddress((void**)&pa,g_a);
    cudaGetSymbolAddress((void**)&pm,g_m);   cudaGetSymbolAddress((void**)&pf,g_f);
    cudaGetSymbolAddress((void**)&w1,g_w1);  cudaGetSymbolAddress((void**)&w2,g_w2);
    cudaGetSymbolAddress((void**)&w3,g_w3);  cudaGetSymbolAddress((void**)&w4,g_w4);

    // smem sizes
    const int S_QKV = 3*((128*40 + 128*40)*2);          // 61440
    const int S_QK  = 1*((128*72 + 64*72)*2);           // 27648
    const int S_AV  = 3*((64*40)*2 + (32*72)*2);        // 29184
    const int S_PRJ = 3*((64*40 + 128*40)*2);           // 46080
    const int S_FC1 = 3*((128*40 + 128*40)*2);          // 61440
    cudaFuncSetAttribute(mma_gemm<128,128,32,1,true>, cudaFuncAttributeMaxDynamicSharedMemorySize, S_QKV);
    cudaFuncSetAttribute(mma_gemm<128,64,64,0,true>,  cudaFuncAttributeMaxDynamicSharedMemorySize, S_QK);
    cudaFuncSetAttribute(mma_gemm<64,64,32,2,false>,  cudaFuncAttributeMaxDynamicSharedMemorySize, S_AV);
    cudaFuncSetAttribute(mma_gemm<64,128,32,3,true>,  cudaFuncAttributeMaxDynamicSharedMemorySize, S_PRJ);
    cudaFuncSetAttribute(mma_gemm<128,128,32,4,true>, cudaFuncAttributeMaxDynamicSharedMemorySize, S_FC1);

    // fused ln1 + weight convert
    pre_kernel<<<4096+27648,256>>>(x,g1,be1,ph1, w_qkv,w_proj,w_fc1,w_fc2, w1,w2,w3,w4);

    GP p{};
    // QKV: h1 @ w_qkv^T + b -> q, k, v
    p.Ah=ph1; p.Bh=w1; p.K=768; p.lda=768; p.ldb=768;
    p.bias=b_qkv; p.o1=pq; p.kd=pk; p.vd=pv;
    mma_gemm<128,128,32,1,true><<<dim3(18,32,1),256,S_QKV>>>(p);

    // QK^T per (b,h): S = Q K^T * 0.125 — single-stage BK=64
    p=GP{}; p.Ah=pq; p.Bh=pk;
    p.K=64; p.lda=64; p.ldb=64; p.sAz=65536; p.sBz=65536; p.sOz=HSs;
    p.o1=pS; p.ldo=1024; p.alpha=0.125f;
    mma_gemm<128,64,64,0,true><<<dim3(16,8,48),256,S_QK>>>(p);

    mixsoftmax<<<ROWS,512>>>(pS,pP,t_before,t_after);

    // AV per (b,h): P[1024,1024] @ V[1024,64] (B row-major via trans-ldmatrix)
    p=GP{}; p.Ah=pP; p.Bh=pv;
    p.K=1024; p.lda=1024; p.ldb=64; p.sAz=HSs; p.sBz=65536;
    p.o1=pa;
    mma_gemm<64,64,32,2,false><<<dim3(1,16,48),256,S_AV>>>(p);

    // proj + bias + residual(x) -> x2
    p=GP{}; p.Ah=pa; p.Bh=w2;
    p.K=768; p.lda=768; p.ldb=768; p.bias=b_proj; p.res=x; p.outf=px2; p.ldo=768;
    mma_gemm<64,128,32,3,true><<<dim3(6,64,1),256,S_PRJ>>>(p);

    ln_kernel<<<ROWS,256>>>(px2,g2,be2,ph2,nullptr);
    dwln_kernel<<<ROWS,256>>>(ph2,dw_w,dw_b,gm,bm,pm);

    // fc1 + bias + gelu -> f
    p=GP{}; p.Ah=pm; p.Bh=w3;
    p.K=768; p.lda=768; p.ldb=768; p.bias=b_fc1; p.o1=pf; p.ldoh=3072;
    mma_gemm<128,128,32,4,true><<<dim3(24,32,1),256,S_FC1>>>(p);

    // fc2 + bias + residual(x2) -> out
    p=GP{}; p.Ah=pf; p.Bh=w4;
    p.K=3072; p.lda=3072; p.ldb=3072; p.bias=b_fc2; p.res=px2; p.outf=out; p.ldo=768;
    mma_gemm<64,128,32,3,true><<<dim3(6,64,1),256,S_PRJ>>>(p);
}

// round 16
// speedup vs baseline: 1.7415x; 1.0394x over previous
#include <cuda_runtime.h>
#include <cuda_fp16.h>
#include <math.h>
#include <stdint.h>
typedef __half hf;

#define NHEAD 12
#define ROWS  4096
#define HSs   1048576LL

// ---------------- scratch ----------------
__device__ __align__(16) hf    g_S  [50331648];
__device__ __align__(16) hf    g_P  [50331648];     // E (unnormalized exp)
__device__ __align__(16) hf    g_q  [3145728];
__device__ __align__(16) hf    g_k  [3145728];
__device__ __align__(16) hf    g_v  [3145728];
__device__ __align__(16) hf    g_h1 [3145728];
__device__ __align__(16) hf    g_a  [3145728];
__device__ __align__(16) hf    g_m  [3145728];
__device__ __align__(16) hf    g_f  [12582912];
__device__ __align__(16) float g_x2 [3145728], g_h2[3145728];   // g_h2 doubles as Y before ln2
__device__ __align__(16) float g_rin[49152];
__device__ __align__(16) hf    g_w1 [1769472];
__device__ __align__(16) hf    g_w2 [589824];
__device__ __align__(16) hf    g_w3 [2359296];
__device__ __align__(16) hf    g_w4 [2359296];

__device__ __forceinline__ uint32_t smem_u32(const void* p){
    uint32_t a; asm("{ .reg .u64 t; cvta.to.shared.u64 t, %1; cvt.u32.u64 %0, t; }":"=r"(a):"l"(p)); return a;
}
#define LDM4(r0,r1,r2,r3,ad) asm volatile("ldmatrix.sync.aligned.m8n8.x4.shared.b16 {%0,%1,%2,%3},[%4];" \
    : "=r"(r0),"=r"(r1),"=r"(r2),"=r"(r3):"r"(ad))
#define LDM4T(r0,r1,r2,r3,ad) asm volatile("ldmatrix.sync.aligned.m8n8.x4.trans.shared.b16 {%0,%1,%2,%3},[%4];" \
    : "=r"(r0),"=r"(r1),"=r"(r2),"=r"(r3):"r"(ad))
#define MMA(d,a,b) asm volatile( \
    "mma.sync.aligned.m16n8k16.row.col.f32.f16.f16.f32 {%0,%1,%2,%3},{%4,%5,%6,%7},{%8,%9},{%0,%1,%2,%3};" \
    : "+f"((d)[0]),"+f"((d)[1]),"+f"((d)[2]),"+f"((d)[3]) \
    : "r"((a)[0]),"r"((a)[1]),"r"((a)[2]),"r"((a)[3]),"r"((b)[0]),"r"((b)[1]))
#define CPA(dst,src) asm volatile("cp.async.cg.shared.global [%0],[%1],16;"::"r"(dst),"l"(src))
#define CPCOMMIT()   asm volatile("cp.async.commit_group;":::"memory")
#define CPWAIT0()    asm volatile("cp.async.wait_group 0;":::"memory")
#define CPWAIT1()    asm volatile("cp.async.wait_group 1;":::"memory")

__device__ __forceinline__ void st_h2(hf* p, float a, float b){
    __half2 t; t.x=__float2half_rn(a); t.y=__float2half_rn(b); *(__half2*)p = t;
}

struct GP {
    const hf *Ah,*Bh;
    int K, lda, ldb;
    long long sAz, sBz, sOz;
    float alpha;
    const float *bias, *res;
    float *outf; int ldo;
    hf *o1; int ldoh;
    hf *kd,*vd;
};

// C[M,N] = A[M,K] @ op(B), single fp16 product.
// EPI: 0=alpha->fp16 batched, 1=QKV scatter, 3=bias+res f32, 4=bias+gelu fp16, 5=fp32 batched
template<int BM,int BN,int BK,int EPI,bool BT>
__global__ void __launch_bounds__(256) mma_gemm(GP p){
    constexpr int WARPS_N = BN/32;
    constexpr int WARPS_M = 8/WARPS_N;
    constexpr int WM = BM/WARPS_M;
    constexpr int MT = WM/16;
    constexpr int APAD = BK+8;
    constexpr int BPAD = BT ? (BK+8) : (BN+8);
    constexpr int ABYT = BM*APAD*2;
    constexpr int BBYT = BT ? (BN*BPAD*2) : (BK*BPAD*2);
    constexpr int STG  = ABYT + BBYT;

    extern __shared__ char dsm[];
    const uint32_t sb = smem_u32(dsm);
    const int tid=threadIdx.x, wid=tid>>5, lane=tid&31;
    const int z=blockIdx.z, m0=blockIdx.y*BM, n0=blockIdx.x*BN;
    const int wm_=wid/WARPS_N, wn_=wid%WARPS_N;

    const hf* Ah=p.Ah+(long long)z*p.sAz;
    const hf* Bh=p.Bh+(long long)z*p.sBz;

    float acc[MT][4][4];
    #pragma unroll
    for(int i=0;i<MT;i++)
        #pragma unroll
        for(int j=0;j<4;j++)
            #pragma unroll
            for(int e=0;e<4;e++) acc[i][j][e]=0.f;

    auto load_stage=[&](int t,int s){
        const long long k0=(long long)t*BK;
        const uint32_t b0 = sb + s*STG;
        #pragma unroll
        for(int i=tid;i<BM*(BK/8);i+=256){
            int row=i/(BK/8), seg=i%(BK/8);
            uint32_t d = b0 + (row*APAD+seg*8)*2;
            long long g=(long long)(m0+row)*p.lda + k0 + seg*8;
            CPA(d, Ah+g);
        }
        if(BT){
            #pragma unroll
            for(int i=tid;i<BN*(BK/8);i+=256){
                int row=i/(BK/8), seg=i%(BK/8);
                uint32_t d=b0+ABYT+(row*BPAD+seg*8)*2;
                long long g=(long long)(n0+row)*p.ldb + k0 + seg*8;
                CPA(d, Bh+g);
            }
        } else {
            #pragma unroll
            for(int i=tid;i<BK*(BN/8);i+=256){
                int row=i/(BN/8), seg=i%(BN/8);
                uint32_t d=b0+ABYT+(row*BPAD+seg*8)*2;
                long long g=(long long)(k0+row)*p.ldb + n0 + seg*8;
                CPA(d, Bh+g);
            }
        }
        CPCOMMIT();
    };

    auto compute=[&](int s){
        const uint32_t bA=sb+s*STG, bB=bA+ABYT;
        #pragma unroll
        for(int kk=0;kk<BK;kk+=16){
            uint32_t bh[4][2];
            #pragma unroll
            for(int nt=0;nt<2;nt++){
                if(BT){
                    int row = wn_*32 + nt*16 + (lane&7) + ((lane>>4)&1)*8;
                    int ko  = kk + ((lane>>3)&1)*8;
                    uint32_t off=(uint32_t)(row*BPAD+ko)*2;
                    LDM4(bh[2*nt][0],bh[2*nt][1],bh[2*nt+1][0],bh[2*nt+1][1], bB+off);
                } else {
                    int kb = kk + (lane&7) + ((lane>>3)&1)*8;
                    int nb = wn_*32 + nt*16 + ((lane>>4)&1)*8;
                    uint32_t off=(uint32_t)(kb*BPAD+nb)*2;
                    LDM4T(bh[2*nt][0],bh[2*nt][1],bh[2*nt+1][0],bh[2*nt+1][1], bB+off);
                }
            }
            #pragma unroll
            for(int mi=0;mi<MT;mi++){
                int row = wm_*WM + mi*16 + (lane&7) + ((lane>>3)&1)*8;
                int ko  = kk + ((lane>>4)&1)*8;
                uint32_t off=(uint32_t)(row*APAD+ko)*2;
                uint32_t ah[4];
                LDM4(ah[0],ah[1],ah[2],ah[3], bA+off);
                #pragma unroll
                for(int ni=0;ni<4;ni++) MMA(acc[mi][ni],ah,bh[ni]);
            }
        }
    };

    const int T = p.K/BK;
    load_stage(0,0);
    if(T>1) load_stage(1,1);
    for(int t=0;t<T;t++){
        if(t+1<T){ CPWAIT1(); } else { CPWAIT0(); }
        __syncthreads();
        if(t+2<T) load_stage(t+2,(t+2)%3);
        compute(t%3);
    }

    // -------- epilogue --------
    const int rb = m0 + wm_*WM, cbse = n0 + wn_*32;
    #pragma unroll
    for(int mi=0;mi<MT;mi++){
        #pragma unroll
        for(int ni=0;ni<4;ni++){
            #pragma unroll
            for(int half=0;half<2;half++){
                int r = rb + mi*16 + (lane>>2) + half*8;
                int c = cbse + ni*8 + (lane&3)*2;
                float v0=acc[mi][ni][half*2], v1=acc[mi][ni][half*2+1];
                if(EPI==0){
                    st_h2(p.o1 + (long long)z*p.sOz + (long long)r*p.ldo + c,
                          v0*p.alpha, v1*p.alpha);
                } else if(EPI==1){
                    v0+=p.bias[c]; v1+=p.bias[c+1];
                    int b=r>>10, n=r&1023;
                    hf* dst = (c<768)?p.o1 : ((c<1536)?p.kd:p.vd);
                    int cc  = (c<768)?c   : ((c<1536)?c-768:c-1536);
                    int hh=cc>>6, d=cc&63;
                    long long o=((long long)(b*12+hh)*1024+n)*64+d;
                    st_h2(dst+o, v0, v1);
                } else if(EPI==3){
                    long long o=(long long)r*p.ldo + c;
                    float2 rr=*(const float2*)(p.res+o);
                    float2 ov; ov.x=v0+p.bias[c]+rr.x; ov.y=v1+p.bias[c+1]+rr.y;
                    *(float2*)(p.outf+o)=ov;
                } else if(EPI==4){
                    v0+=p.bias[c]; v1+=p.bias[c+1];
                    v0=0.5f*v0*(1.0f+erff(v0*0.70710678118654752f));
                    v1=0.5f*v1*(1.0f+erff(v1*0.70710678118654752f));
                    st_h2(p.o1+(long long)r*p.ldoh+c, v0, v1);
                } else if(EPI==5){
                    float2 ov; ov.x=v0; ov.y=v1;
                    *(float2*)(p.outf + (long long)z*p.sOz + (long long)r*p.ldo + c)=ov;
                }
            }
        }
    }
}

// ---------------- LayerNorm body ----------------
__device__ __forceinline__ void ln_body(const float* x, const float* g, const float* b,
                                        float* outf, hf* oh, long long row, int tid){
    float xv[3], s=0.f, ss=0.f;
    #pragma unroll
    for(int i=0;i<3;i++){ float v=x[tid+i*256]; xv[i]=v; s+=v; ss+=v*v; }
    __shared__ float red[64];
    #pragma unroll
    for(int o=16;o>0;o>>=1){ s+=__shfl_down_sync(~0u,s,o); ss+=__shfl_down_sync(~0u,ss,o); }
    int warp=tid>>5, lane=tid&31;
    if(lane==0){ red[warp]=s; red[32+warp]=ss; }
    __syncthreads();
    if(warp==0){
        s=(lane<8)?red[lane]:0.f; ss=(lane<8)?red[32+lane]:0.f;
        #pragma unroll
        for(int o=4;o>0;o>>=1){ s+=__shfl_down_sync(~0u,s,o); ss+=__shfl_down_sync(~0u,ss,o); }
        if(lane==0){ red[0]=s; red[1]=ss; }
    }
    __syncthreads();
    float mu=red[0]*(1.f/768), var=red[1]*(1.f/768)-mu*mu, rstd=rsqrtf(var+1e-5f);
    #pragma unroll
    for(int i=0;i<3;i++){
        int c=tid+i*256;
        float v=(xv[i]-mu)*rstd*g[c]+b[c];
        long long o=row*768+c;
        if(outf) outf[o]=v;
        if(oh) oh[o]=__float2half_rn(v);
    }
}

__global__ void ln_kernel(const float* __restrict__ in, const float* __restrict__ g,
                          const float* __restrict__ b, float* __restrict__ outf,
                          hf* __restrict__ oh){
    ln_body(in + (long long)blockIdx.x*768, g, b, outf, oh, blockIdx.x, threadIdx.x);
}

// ---------------- fused wconv + ln1 ----------------
__global__ void pre_kernel(const float* __restrict__ x, const float* __restrict__ g1,
                           const float* __restrict__ be1, hf* __restrict__ oh,
                           const float* __restrict__ w1,const float* __restrict__ w2,
                           const float* __restrict__ w3,const float* __restrict__ w4,
                           hf* o1,hf* o2,hf* o3,hf* o4){
    int bid=blockIdx.x;
    if(bid<4096){
        ln_body(x + (long long)bid*768, g1, be1, nullptr, oh, bid, threadIdx.x);
    } else {
        int i=(bid-4096)*256+threadIdx.x;
        const float* s; hf *ohw; int j=i;
        if(j<1769472){ s=w1; ohw=o1; }
        else if((j-=1769472)<589824){ s=w2; ohw=o2; }
        else if((j-=589824)<2359296){ s=w3; ohw=o3; }
        else { j-=2359296; s=w4; ohw=o4; }
        ohw[j]=__float2half_rn(s[j]);
    }
}

// ---------------- single-pass mix -> exp -> E + rin ----------------
__global__ void __launch_bounds__(512) mixsoftmax(
    const hf* __restrict__ S, hf* __restrict__ E, float* __restrict__ rinG,
    const float* __restrict__ tb){
    __shared__ __half2 tbs2[144];
    __shared__ float wsum[16][12];
    int tid=threadIdx.x, warp=tid>>5, lane=tid&31;
    if(tid<144) tbs2[tid]=__float2half2_rn(tb[tid]);
    __syncthreads();
    int bn=blockIdx.x, b=bn>>10, n=bn&1023;
    long long base=((long long)b*NHEAD*1024+n)*1024;
    const __half2* Sb=(const __half2*)(S+base);
    __half2* Eb=(__half2*)(E+base);
    const int mp=tid;
    float sm[12];
    {
        __half2 s2[12];
        #pragma unroll
        for(int h=0;h<12;h++) s2[h]=Sb[(uint32_t)(h*524288)+mp];
        #pragma unroll
        for(int g=0;g<12;g++){
            __half2 v=__float2half2_rn(0.f);
            #pragma unroll
            for(int h=0;h<12;h++) v=__hfma2(tbs2[g*12+h],s2[h],v);
            __half2 e=h2exp(v);
            Eb[(uint32_t)(g*524288)+mp]=e;
            float2 ef=__half22float2(e);
            sm[g]=ef.x+ef.y;
        }
    }
    #pragma unroll
    for(int o=16;o>0;o>>=1){
        #pragma unroll
        for(int g=0;g<12;g++) sm[g]+=__shfl_xor_sync(~0u,sm[g],o);
    }
    if(lane==0){
        #pragma unroll
        for(int g=0;g<12;g++) wsum[warp][g]=sm[g];
    }
    __syncthreads();
    if(tid<12){
        float t=0.f;
        #pragma unroll
        for(int w=0;w<16;w++) t+=wsum[w][tid];
        rinG[(b*12+tid)*1024+n]=1.f/t;
    }
}

// ---------------- combine: attn[b,n,g*64+d] = sum_h ta[g,h]*rin[b,h,n]*Y[b,h,n,d] ----------------
__global__ void __launch_bounds__(256) combine_kernel(
    const float* __restrict__ Y, const float* __restrict__ rinG,
    const float* __restrict__ ta, hf* __restrict__ attn){
    __shared__ float tas[144], rr[4][12];
    int tid=threadIdx.x;
    if(tid<144) tas[tid]=ta[tid];
    int bn0=blockIdx.x*4;
    if(tid<48){
        int sub=tid/12, h=tid-sub*12;
        int bn=bn0+sub, b=bn>>10, n=bn&1023;
        rr[sub][h]=rinG[(b*12+h)*1024+n];
    }
    __syncthreads();
    int sub=tid>>6, d=tid&63;
    int bn=bn0+sub, b=bn>>10, n=bn&1023;
    float y[12];
    #pragma unroll
    for(int h=0;h<12;h++)
        y[h]=Y[((long long)(b*12+h))*65536 + n*64 + d]*rr[sub][h];
    #pragma unroll
    for(int g=0;g<12;g++){
        float v=0.f;
        #pragma unroll
        for(int h=0;h<12;h++) v=fmaf(tas[g*12+h],y[h],v);
        attn[(long long)bn*768 + g*64 + d]=__float2half_rn(v);
    }
}

// ---------------- fused depthwise conv + LN(gm,bm) ----------------
__global__ void dwln_kernel(const float* __restrict__ in, const float* __restrict__ w,
                            const float* __restrict__ bias, const float* __restrict__ gm,
                            const float* __restrict__ bm, hf* __restrict__ om){
    int row=blockIdx.x, tid=threadIdx.x;
    int b=row>>10, n=row&1023;
    const float* xp = in + (long long)b*1024*768;
    float acc[3], s=0.f, ss=0.f;
    #pragma unroll
    for(int i=0;i<3;i++){
        int c=tid+i*256;
        float a=bias[c];
        #pragma unroll
        for(int k=0;k<7;k++){
            int m=n+k-3;
            if(m>=0 && m<1024) a+=w[c*7+k]*xp[(long long)m*768+c];
        }
        acc[i]=a; s+=a; ss+=a*a;
    }
    __shared__ float red[64];
    #pragma unroll
    for(int o=16;o>0;o>>=1){ s+=__shfl_down_sync(~0u,s,o); ss+=__shfl_down_sync(~0u,ss,o); }
    int warp=tid>>5, lane=tid&31;
    if(lane==0){ red[warp]=s; red[32+warp]=ss; }
    __syncthreads();
    if(warp==0){
        s=(lane<8)?red[lane]:0.f; ss=(lane<8)?red[32+lane]:0.f;
        #pragma unroll
        for(int o=4;o>0;o>>=1){ s+=__shfl_down_sync(~0u,s,o); ss+=__shfl_down_sync(~0u,ss,o); }
        if(lane==0){ red[0]=s; red[1]=ss; }
    }
    __syncthreads();
    float mu=red[0]*(1.f/768), var=red[1]*(1.f/768)-mu*mu, rstd=rsqrtf(var+1e-5f);
    #pragma unroll
    for(int i=0;i<3;i++){
        int c=tid+i*256;
        om[(long long)row*768+c]=__float2half_rn((acc[i]-mu)*rstd*gm[c]+bm[c]);
    }
}

// ---------------- launch ----------------
extern "C" void kernel_launch(void* const* d_in, const int* in_sizes, int n_in,
                              void* d_out, int out_size){
    const float *x=(const float*)d_in[0], *w_qkv=(const float*)d_in[1], *b_qkv=(const float*)d_in[2];
    const float *w_proj=(const float*)d_in[3], *b_proj=(const float*)d_in[4];
    const float *w_fc1=(const float*)d_in[5], *b_fc1=(const float*)d_in[6];
    const float *w_fc2=(const float*)d_in[7], *b_fc2=(const float*)d_in[8];
    const float *t_before=(const float*)d_in[9], *t_after=(const float*)d_in[10];
    const float *g1=(const float*)d_in[11], *be1=(const float*)d_in[12];
    const float *g2=(const float*)d_in[13], *be2=(const float*)d_in[14];
    const float *dw_w=(const float*)d_in[15], *dw_b=(const float*)d_in[16];
    const float *gm=(const float*)d_in[17], *bm=(const float*)d_in[18];
    float* out=(float*)d_out;

    float *px2,*ph2,*prin;
    hf *pS,*pP,*pq,*pk,*pv,*ph1,*pa,*pm,*pf,*w1,*w2,*w3,*w4;
    cudaGetSymbolAddress((void**)&pS,g_S);   cudaGetSymbolAddress((void**)&px2,g_x2);
    cudaGetSymbolAddress((void**)&ph2,g_h2); cudaGetSymbolAddress((void**)&prin,g_rin);
    cudaGetSymbolAddress((void**)&pP,g_P);   cudaGetSymbolAddress((void**)&pq,g_q);
    cudaGetSymbolAddress((void**)&pk,g_k);   cudaGetSymbolAddress((void**)&pv,g_v);
    cudaGetSymbolAddress((void**)&ph1,g_h1); cudaGetSymbolAddress((void**)&pa,g_a);
    cudaGetSymbolAddress((void**)&pm,g_m);   cudaGetSymbolAddress((void**)&pf,g_f);
    cudaGetSymbolAddress((void**)&w1,g_w1);  cudaGetSymbolAddress((void**)&w2,g_w2);
    cudaGetSymbolAddress((void**)&w3,g_w3);  cudaGetSymbolAddress((void**)&w4,g_w4);

    // smem sizes
    const int S_QKV = 3*((128*40 + 128*40)*2);          // 61440
    const int S_QK  = 1*((128*72 + 64*72)*2);           // 27648
    const int S_AV  = 3*((64*40)*2 + (32*72)*2);        // 29184
    const int S_PRJ = 3*((64*40 + 128*40)*2);           // 46080
    const int S_FC1 = 3*((128*40 + 128*40)*2);          // 61440
    cudaFuncSetAttribute(mma_gemm<128,128,32,1,true>, cudaFuncAttributeMaxDynamicSharedMemorySize, S_QKV);
    cudaFuncSetAttribute(mma_gemm<128,64,64,0,true>,  cudaFuncAttributeMaxDynamicSharedMemorySize, S_QK);
    cudaFuncSetAttribute(mma_gemm<64,64,32,5,false>,  cudaFuncAttributeMaxDynamicSharedMemorySize, S_AV);
    cudaFuncSetAttribute(mma_gemm<64,128,32,3,true>,  cudaFuncAttributeMaxDynamicSharedMemorySize, S_PRJ);
    cudaFuncSetAttribute(mma_gemm<128,128,32,4,true>, cudaFuncAttributeMaxDynamicSharedMemorySize, S_FC1);

    // fused ln1 + weight convert
    pre_kernel<<<4096+27648,256>>>(x,g1,be1,ph1, w_qkv,w_proj,w_fc1,w_fc2, w1,w2,w3,w4);

    GP p{};
    // QKV: h1 @ w_qkv^T + b -> q, k, v
    p.Ah=ph1; p.Bh=w1; p.K=768; p.lda=768; p.ldb=768;
    p.bias=b_qkv; p.o1=pq; p.kd=pk; p.vd=pv;
    mma_gemm<128,128,32,1,true><<<dim3(18,32,1),256,S_QKV>>>(p);

    // QK^T per (b,h): S = Q K^T * 0.125 — single-stage BK=64
    p=GP{}; p.Ah=pq; p.Bh=pk;
    p.K=64; p.lda=64; p.ldb=64; p.sAz=65536; p.sBz=65536; p.sOz=HSs;
    p.o1=pS; p.ldo=1024; p.alpha=0.125f;
    mma_gemm<128,64,64,0,true><<<dim3(16,8,48),256,S_QK>>>(p);

    // single-pass mix->exp->E + rin
    mixsoftmax<<<ROWS,512>>>(pS,pP,prin,t_before);

    // AV per (b,h): E[1024,1024] @ V[1024,64] -> Y fp32 [b*12+h,1024,64] (reuses g_h2)
    p=GP{}; p.Ah=pP; p.Bh=pv;
    p.K=1024; p.lda=1024; p.ldb=64; p.sAz=HSs; p.sBz=65536; p.sOz=65536;
    p.outf=ph2; p.ldo=64; p.alpha=1.0f;
    mma_gemm<64,64,32,5,false><<<dim3(1,16,48),256,S_AV>>>(p);

    // combine: normalize + after-mix -> attn fp16
    combine_kernel<<<ROWS/4,256>>>(ph2,prin,t_after,pa);

    // proj + bias + residual(x) -> x2
    p=GP{}; p.Ah=pa; p.Bh=w2;
    p.K=768; p.lda=768; p.ldb=768; p.bias=b_proj; p.res=x; p.outf=px2; p.ldo=768;
    mma_gemm<64,128,32,3,true><<<dim3(6,64,1),256,S_PRJ>>>(p);

    ln_kernel<<<ROWS,256>>>(px2,g2,be2,ph2,nullptr);
    dwln_kernel<<<ROWS,256>>>(ph2,dw_w,dw_b,gm,bm,pm);

    // fc1 + bias + gelu -> f
    p=GP{}; p.Ah=pm; p.Bh=w3;
    p.K=768; p.lda=768; p.ldb=768; p.bias=b_fc1; p.o1=pf; p.ldoh=3072;
    mma_gemm<128,128,32,4,true><<<dim3(24,32,1),256,S_FC1>>>(p);

    // fc2 + bias + residual(x2) -> out
    p=GP{}; p.Ah=pf; p.Bh=w4;
    p.K=3072; p.lda=3072; p.ldb=3072; p.bias=b_fc2; p.res=px2; p.outf=out; p.ldo=768;
    mma_gemm<64,128,32,3,true><<<dim3(6,64,1),256,S_PRJ>>>(p);
}